// round 13
// baseline (speedup 1.0000x reference)
#include <cuda_runtime.h>
#include <cuda_bf16.h>
#include <cstdint>

#define Bk 2048
#define Tk 100
#define Hk 256
#define Lk 128
#define NVk 5
#define Rk 16
#define OW 512
#define HSTR 20     // hs/rh k-row stride in floats
#define ESTR 17     // pex entry stride in ull

#define RH_OFF   (Hk * HSTR)                 // 5120 floats
#define PEX_OFF  (2 * Hk * HSTR)             // 10240 floats
#define PEX_FL   (2 * 256 * ESTR)            // 8704 floats (as ull region)
#define XW_OFF   (PEX_OFF + PEX_FL)          // 18944
#define XW_FL    (3 * 6 * Hk)                // 4608 (x-weights + bias, 3 gates)
#define XALL_OFF (XW_OFF + XW_FL)            // 23552
#define XALL_FL  (Tk * NVk * 16)             // 8000: xall[(t*5+v)*16 + r]
#define SMEM_F   (XALL_OFF + XALL_FL)        // 31552 floats = 126208 B

typedef unsigned long long ull;

// Pairwise barrier between kh-partner warps (w and w^8): ids 1..8, 64 threads.
#define PAIRBAR(bid) asm volatile("bar.sync %0, 64;" :: "r"(bid) : "memory")
// rh-scoped barrier: the 8 warps of one rh half (ids 9,10), 256 threads.
#define RHBAR(rhid)  asm volatile("bar.sync %0, 256;" :: "r"(9 + (rhid)) : "memory")

// Stage-1 weights as bf16 quads: g_wzrh[k*128 + jp] = (wz_j0,wr_j0,wz_j1,wr_j1)
// in 8 bytes -> LDG.64 (2 wf). bf16 -> f32 is shift/mask (ALU), NOT cvt.
__device__ __align__(8) ull g_wzrh[Hk * 128];

__device__ __forceinline__ void fma2(ull& d, ull a, ull b) {
    asm("fma.rn.f32x2 %0, %1, %2, %0;" : "+l"(d) : "l"(a), "l"(b));
}
__device__ __forceinline__ void add2(ull& d, ull a) {
    asm("add.rn.f32x2 %0, %0, %1;" : "+l"(d) : "l"(a));
}
__device__ __forceinline__ ull pack2(float lo, float hi) {
    ull r; asm("mov.b64 %0, {%1, %2};" : "=l"(r) : "f"(lo), "f"(hi)); return r;
}
__device__ __forceinline__ ull dup32(unsigned v) {
    ull r; asm("mov.b64 %0, {%1, %1};" : "=l"(r) : "r"(v)); return r;
}
__device__ __forceinline__ float2 unpack2(ull p) {
    float2 f; asm("mov.b64 {%0, %1}, %2;" : "=f"(f.x), "=f"(f.y) : "l"(p)); return f;
}
// bf16 quad -> four lane-duplicated f32x2 multipliers, pure ALU (shift/mask/mov).
__device__ __forceinline__ void unpack_wbf(ull w, ull& wzz0, ull& wrr0,
                                           ull& wzz1, ull& wrr1) {
    unsigned u0 = (unsigned)w, u1 = (unsigned)(w >> 32);
    wzz0 = dup32(u0 << 16);
    wrr0 = dup32(u0 & 0xFFFF0000u);
    wzz1 = dup32(u1 << 16);
    wrr1 = dup32(u1 & 0xFFFF0000u);
}
__device__ __forceinline__ float sigmoidf_fast(float x) {
    return 1.0f / (1.0f + __expf(-x));
}
// volatile smem v2 load: keeps loop-invariant xw out of persistent registers.
__device__ __forceinline__ float2 lds2v(uint32_t a) {
    float2 f;
    asm volatile("ld.shared.v2.f32 {%0,%1},[%2];" : "=f"(f.x), "=f"(f.y) : "r"(a));
    return f;
}
__device__ __forceinline__ void fma8s(float acc[8], float4 a0, float4 a1, float wv) {
    acc[0] = fmaf(a0.x, wv, acc[0]); acc[1] = fmaf(a0.y, wv, acc[1]);
    acc[2] = fmaf(a0.z, wv, acc[2]); acc[3] = fmaf(a0.w, wv, acc[3]);
    acc[4] = fmaf(a1.x, wv, acc[4]); acc[5] = fmaf(a1.y, wv, acc[5]);
    acc[6] = fmaf(a1.z, wv, acc[6]); acc[7] = fmaf(a1.w, wv, acc[7]);
}

__global__ void repack_kernel(const float* __restrict__ Wz,
                              const float* __restrict__ Wr) {
    int idx = blockIdx.x * blockDim.x + threadIdx.x;   // 32768 over [k][jp]
    int k = idx >> 7, jp = idx & 127;
    int j0 = jp << 1;
    unsigned z0 = __bfloat16_as_ushort(__float2bfloat16(Wz[(NVk + k) * Hk + j0]));
    unsigned r0 = __bfloat16_as_ushort(__float2bfloat16(Wr[(NVk + k) * Hk + j0]));
    unsigned z1 = __bfloat16_as_ushort(__float2bfloat16(Wz[(NVk + k) * Hk + j0 + 1]));
    unsigned r1 = __bfloat16_as_ushort(__float2bfloat16(Wr[(NVk + k) * Hk + j0 + 1]));
    unsigned u0 = z0 | (r0 << 16);
    unsigned u1 = z1 | (r1 << 16);
    g_wzrh[idx] = (ull)u0 | ((ull)u1 << 32);
}

// 128 blocks x 512 threads. Thread (jp, rh, kh): columns j0=2jp, j1=j0+1;
// accumulates rows [rh*8, rh*8+8) over k-half [kh*128, +128); finalizes
// rows rfin = rh*8 + kh*4 .. +4 after a 2-way partial exchange via smem.
__global__ __launch_bounds__(512, 1)
void gru_decoder_kernel(
    const float* __restrict__ x_seq,
    const float* __restrict__ hidden,
    const float* __restrict__ tree,
    const float* __restrict__ graph,
    const int*   __restrict__ lengths,
    const float* __restrict__ Wcs, const float* __restrict__ bcs,
    const float* __restrict__ Wz,  const float* __restrict__ bz,
    const float* __restrict__ Wr,  const float* __restrict__ br,
    const float* __restrict__ Wh,  const float* __restrict__ bh,
    float* __restrict__ out)
{
    extern __shared__ __align__(16) float smf[];
    float* hsb  = smf;                       // hs[k*HSTR + r]
    float* rhb  = smf + RH_OFF;              // rh[k*HSTR + r]
    ull*   pexu = (ull*)(smf + PEX_OFF);     // exchange buffer
    float* cvb  = smf + PEX_OFF;             // prologue overlay (6144 floats)
    float* xw   = smf + XW_OFF;              // x-weights+bias [g][v(6)][j]
    float* xall = smf + XALL_OFF;            // x preload [(t*5+v)*16 + r]

    const int tid  = threadIdx.x;
    const int jp   = tid & 127;
    const int rh   = (tid >> 7) & 1;
    const int kh   = tid >> 8;
    const int j0   = jp << 1;
    const int rbase = rh << 3;
    const int rfin  = rbase + (kh << 2);
    const int rexp  = rbase + ((1 - kh) << 2);
    const int ep    = (1 - kh) << 1;
    const int op    = kh << 1;
    const int k0    = kh << 7;
    const int row0  = blockIdx.x * Rk;
    const int pbid  = 1 + ((tid >> 5) & 7);

    float* out_newh = out;
    float* out_all  = out + Bk * Hk;
    float* out_seg  = out + Bk * Hk + Bk * Tk * OW;

    // ---- one-time loads ----
    for (int idx = tid; idx < XW_FL; idx += 512) {
        int g = idx / (6 * Hk);
        int vj = idx - g * 6 * Hk;
        int v = vj >> 8, j = vj & 255;
        const float* W = (g == 0) ? Wz : ((g == 1) ? Wr : Wh);
        const float* bb = (g == 0) ? bz : ((g == 1) ? br : bh);
        xw[idx] = (v < NVk) ? W[v * Hk + j] : bb[j];
    }
    for (int idx = tid; idx < Rk * Tk * NVk; idx += 512) {
        int r  = idx / (Tk * NVk);
        int tv = idx - r * (Tk * NVk);
        xall[tv * 16 + r] = x_seq[(row0 + r) * (Tk * NVk) + tv];
    }

    float2 latp[4];
    int    slenr[4];
#pragma unroll
    for (int i = 0; i < 4; i++) {
        int row = row0 + rfin + i;
        latp[i] = (jp < 64)
            ? make_float2(tree[row * Lk + j0], tree[row * Lk + j0 + 1])
            : make_float2(graph[row * Lk + j0 - Lk], graph[row * Lk + j0 - Lk + 1]);
        slenr[i] = lengths[row];
    }

    for (int idx = tid; idx < Rk * (Hk + Lk); idx += 512) {
        int r = idx / (Hk + Lk);
        int k = idx - r * (Hk + Lk);
        cvb[k * 16 + r] = (k < Hk) ? hidden[(row0 + r) * Hk + k]
                                   : graph[(row0 + r) * Lk + (k - Hk)];
    }
    __syncthreads();

    // h0 = relu(cv @ Wcs + bcs)
    {
        const int jc   = tid & 255;
        const int orow = (tid >> 8) << 3;
        float acc[8];
        const float b0 = bcs[jc];
#pragma unroll
        for (int r = 0; r < 8; r++) acc[r] = b0;
        const float* pcs = Wcs + jc;
#pragma unroll 4
        for (int k = 0; k < Hk + Lk; k++) {
            float wv  = pcs[k * Hk];
            float4 a0 = *(const float4*)&cvb[k * 16 + orow];
            float4 a1 = *(const float4*)&cvb[k * 16 + orow + 4];
            fma8s(acc, a0, a1, wv);
        }
#pragma unroll
        for (int r = 0; r < 8; r++) hsb[jc * HSTR + orow + r] = fmaxf(acc[r], 0.0f);
    }
    __syncthreads();   // h0 writer mapping is kh-based: full sync once, pre-loop

    float segj0[4], segj1[4];
#pragma unroll
    for (int i = 0; i < 4; i++) { segj0[i] = -1e30f; segj1[i] = -1e30f; }

    const uint32_t smem_u32 = (uint32_t)__cvta_generic_to_shared(smf);
    const uint32_t xbase    = smem_u32 + (uint32_t)(XW_OFF + j0) * 4u;

    ull* pe = pexu + (rh * 128 + jp) * ESTR + (1 - kh) * 8;
    const ull* po = pexu + (rh * 128 + jp) * ESTR + kh * 8;

    const ull*    pwbase  = g_wzrh + (k0 << 7) + jp;
    const float2* pwhbase = reinterpret_cast<const float2*>(Wh + NVk * Hk) + (k0 << 7) + jp;

    ull wp = pwbase[0];   // prefetch stage1 bf16 weight quad for t=0

    for (int t = 0; t < Tk; t++) {
        if (t) RHBAR(rh);

        const float* xp = xall + t * (NVk * 16) + rexp;

        // ---- stage 1: z & r partials (2 j x 8 rows over own k-half) ----
        ull az0[4], az1[4], ar0[4], ar1[4];
        {
            float2 bz2 = lds2v(xbase + 5u * 1024u);
            float2 br2 = lds2v(xbase + 6144u + 5u * 1024u);
            float vz0[4], vz1[4], vr0[4], vr1[4];
#pragma unroll
            for (int i = 0; i < 4; i++) {
                vz0[i] = bz2.x; vz1[i] = bz2.y; vr0[i] = br2.x; vr1[i] = br2.y;
            }
#pragma unroll
            for (int v = 0; v < NVk; v++) {
                float2 wz = lds2v(xbase + (unsigned)v * 1024u);
                float2 wr = lds2v(xbase + 6144u + (unsigned)v * 1024u);
#pragma unroll
                for (int i = 0; i < 4; i++) {
                    float xv = xp[v * 16 + i];
                    vz0[i] = fmaf(xv, wz.x, vz0[i]); vz1[i] = fmaf(xv, wz.y, vz1[i]);
                    vr0[i] = fmaf(xv, wr.x, vr0[i]); vr1[i] = fmaf(xv, wr.y, vr1[i]);
                }
            }
            az0[ep] = pack2(vz0[0], vz0[1]); az0[ep + 1] = pack2(vz0[2], vz0[3]);
            az1[ep] = pack2(vz1[0], vz1[1]); az1[ep + 1] = pack2(vz1[2], vz1[3]);
            ar0[ep] = pack2(vr0[0], vr0[1]); ar0[ep + 1] = pack2(vr0[2], vr0[3]);
            ar1[ep] = pack2(vr1[0], vr1[1]); ar1[ep + 1] = pack2(vr1[2], vr1[3]);
            az0[op] = 0; az0[op + 1] = 0; az1[op] = 0; az1[op + 1] = 0;
            ar0[op] = 0; ar0[op + 1] = 0; ar1[op] = 0; ar1[op + 1] = 0;
        }
        {
            const char* hp = (const char*)(hsb + k0 * HSTR + rbase);
            {   // peeled kk=0 with prefetched weights
                ull wzz0, wrr0, wzz1, wrr1;
                unpack_wbf(wp, wzz0, wrr0, wzz1, wrr1);
                ulonglong2 hA = *(const ulonglong2*)hp;
                ulonglong2 hB = *(const ulonglong2*)(hp + 16);
                hp += HSTR * 4;
                fma2(az0[0], hA.x, wzz0); fma2(az0[1], hA.y, wzz0);
                fma2(az0[2], hB.x, wzz0); fma2(az0[3], hB.y, wzz0);
                fma2(az1[0], hA.x, wzz1); fma2(az1[1], hA.y, wzz1);
                fma2(az1[2], hB.x, wzz1); fma2(az1[3], hB.y, wzz1);
                fma2(ar0[0], hA.x, wrr0); fma2(ar0[1], hA.y, wrr0);
                fma2(ar0[2], hB.x, wrr0); fma2(ar0[3], hB.y, wrr0);
                fma2(ar1[0], hA.x, wrr1); fma2(ar1[1], hA.y, wrr1);
                fma2(ar1[2], hB.x, wrr1); fma2(ar1[3], hB.y, wrr1);
            }
            const ull* pw = pwbase + 128;
#pragma unroll 4
            for (int kk = 1; kk < 128; kk++) {
                ull wraw = *pw; pw += 128;
                ull wzz0, wrr0, wzz1, wrr1;
                unpack_wbf(wraw, wzz0, wrr0, wzz1, wrr1);
                ulonglong2 hA = *(const ulonglong2*)hp;
                ulonglong2 hB = *(const ulonglong2*)(hp + 16);
                hp += HSTR * 4;
                fma2(az0[0], hA.x, wzz0); fma2(az0[1], hA.y, wzz0);
                fma2(az0[2], hB.x, wzz0); fma2(az0[3], hB.y, wzz0);
                fma2(az1[0], hA.x, wzz1); fma2(az1[1], hA.y, wzz1);
                fma2(az1[2], hB.x, wzz1); fma2(az1[3], hB.y, wzz1);
                fma2(ar0[0], hA.x, wrr0); fma2(ar0[1], hA.y, wrr0);
                fma2(ar0[2], hB.x, wrr0); fma2(ar0[3], hB.y, wrr0);
                fma2(ar1[0], hA.x, wrr1); fma2(ar1[1], hA.y, wrr1);
                fma2(ar1[2], hB.x, wrr1); fma2(ar1[3], hB.y, wrr1);
            }
        }
        // export partner's 4 rows
        pe[0] = az0[ep]; pe[1] = az0[ep + 1]; pe[2] = az1[ep]; pe[3] = az1[ep + 1];
        pe[4] = ar0[ep]; pe[5] = ar0[ep + 1]; pe[6] = ar1[ep]; pe[7] = ar1[ep + 1];
        PAIRBAR(pbid);

        float zv0[4], zv1[4];
        {
            add2(az0[op], po[0]); add2(az0[op + 1], po[1]);
            add2(az1[op], po[2]); add2(az1[op + 1], po[3]);
            add2(ar0[op], po[4]); add2(ar0[op + 1], po[5]);
            add2(ar1[op], po[6]); add2(ar1[op + 1], po[7]);
            float2 z0a = unpack2(az0[op]), z0b = unpack2(az0[op + 1]);
            float2 z1a = unpack2(az1[op]), z1b = unpack2(az1[op + 1]);
            zv0[0] = sigmoidf_fast(z0a.x); zv0[1] = sigmoidf_fast(z0a.y);
            zv0[2] = sigmoidf_fast(z0b.x); zv0[3] = sigmoidf_fast(z0b.y);
            zv1[0] = sigmoidf_fast(z1a.x); zv1[1] = sigmoidf_fast(z1a.y);
            zv1[2] = sigmoidf_fast(z1b.x); zv1[3] = sigmoidf_fast(z1b.y);
            float2 r0a = unpack2(ar0[op]), r0b = unpack2(ar0[op + 1]);
            float2 r1a = unpack2(ar1[op]), r1b = unpack2(ar1[op + 1]);
            float2 h0a = *(const float2*)&hsb[j0 * HSTR + rfin];
            float2 h0b = *(const float2*)&hsb[j0 * HSTR + rfin + 2];
            float2 h1a = *(const float2*)&hsb[(j0 + 1) * HSTR + rfin];
            float2 h1b = *(const float2*)&hsb[(j0 + 1) * HSTR + rfin + 2];
            *(ull*)&rhb[j0 * HSTR + rfin] =
                pack2(sigmoidf_fast(r0a.x) * h0a.x, sigmoidf_fast(r0a.y) * h0a.y);
            *(ull*)&rhb[j0 * HSTR + rfin + 2] =
                pack2(sigmoidf_fast(r0b.x) * h0b.x, sigmoidf_fast(r0b.y) * h0b.y);
            *(ull*)&rhb[(j0 + 1) * HSTR + rfin] =
                pack2(sigmoidf_fast(r1a.x) * h1a.x, sigmoidf_fast(r1a.y) * h1a.y);
            *(ull*)&rhb[(j0 + 1) * HSTR + rfin + 2] =
                pack2(sigmoidf_fast(r1b.x) * h1b.x, sigmoidf_fast(r1b.y) * h1b.y);
        }

        // ---- stage 2 x-part init (rhb-independent; before rh barrier) ----
        ull ah0[4], ah1[4];
        {
            float2 bh2 = lds2v(xbase + 12288u + 5u * 1024u);
            float vh0[4], vh1[4];
#pragma unroll
            for (int i = 0; i < 4; i++) { vh0[i] = bh2.x; vh1[i] = bh2.y; }
#pragma unroll
            for (int v = 0; v < NVk; v++) {
                float2 wh = lds2v(xbase + 12288u + (unsigned)v * 1024u);
#pragma unroll
                for (int i = 0; i < 4; i++) {
                    float xv = xp[v * 16 + i];
                    vh0[i] = fmaf(xv, wh.x, vh0[i]); vh1[i] = fmaf(xv, wh.y, vh1[i]);
                }
            }
            ah0[ep] = pack2(vh0[0], vh0[1]); ah0[ep + 1] = pack2(vh0[2], vh0[3]);
            ah1[ep] = pack2(vh1[0], vh1[1]); ah1[ep + 1] = pack2(vh1[2], vh1[3]);
            ah0[op] = 0; ah0[op + 1] = 0; ah1[op] = 0; ah1[op + 1] = 0;
        }
        float2 whp = pwhbase[0];
        RHBAR(rh);

        {
            const char* rp = (const char*)(rhb + k0 * HSTR + rbase);
            {   // peeled kk=0
                ulonglong2 rA = *(const ulonglong2*)rp;
                ulonglong2 rB = *(const ulonglong2*)(rp + 16);
                rp += HSTR * 4;
                ull whh0 = pack2(whp.x, whp.x), whh1 = pack2(whp.y, whp.y);
                fma2(ah0[0], rA.x, whh0); fma2(ah0[1], rA.y, whh0);
                fma2(ah0[2], rB.x, whh0); fma2(ah0[3], rB.y, whh0);
                fma2(ah1[0], rA.x, whh1); fma2(ah1[1], rA.y, whh1);
                fma2(ah1[2], rB.x, whh1); fma2(ah1[3], rB.y, whh1);
            }
            const float2* pwh = pwhbase + 128;
#pragma unroll 8
            for (int kk = 1; kk < 128; kk++) {
                float2 wh = *pwh; pwh += 128;
                ulonglong2 rA = *(const ulonglong2*)rp;
                ulonglong2 rB = *(const ulonglong2*)(rp + 16);
                rp += HSTR * 4;
                ull whh0 = pack2(wh.x, wh.x), whh1 = pack2(wh.y, wh.y);
                fma2(ah0[0], rA.x, whh0); fma2(ah0[1], rA.y, whh0);
                fma2(ah0[2], rB.x, whh0); fma2(ah0[3], rB.y, whh0);
                fma2(ah1[0], rA.x, whh1); fma2(ah1[1], rA.y, whh1);
                fma2(ah1[2], rB.x, whh1); fma2(ah1[3], rB.y, whh1);
            }
        }
        pe[0] = ah0[ep]; pe[1] = ah0[ep + 1]; pe[2] = ah1[ep]; pe[3] = ah1[ep + 1];
        PAIRBAR(pbid);

        // ---- combine + epilogue for own 2j x 4 rows ----
        {
            add2(ah0[op], po[0]); add2(ah0[op + 1], po[1]);
            add2(ah1[op], po[2]); add2(ah1[op + 1], po[3]);
            float2 p0a = unpack2(ah0[op]), p0b = unpack2(ah0[op + 1]);
            float2 p1a = unpack2(ah1[op]), p1b = unpack2(ah1[op + 1]);
            float pre0[4] = {tanhf(p0a.x), tanhf(p0a.y), tanhf(p0b.x), tanhf(p0b.y)};
            float pre1[4] = {tanhf(p1a.x), tanhf(p1a.y), tanhf(p1b.x), tanhf(p1b.y)};
            float2 h0a = *(const float2*)&hsb[j0 * HSTR + rfin];
            float2 h0b = *(const float2*)&hsb[j0 * HSTR + rfin + 2];
            float2 h1a = *(const float2*)&hsb[(j0 + 1) * HSTR + rfin];
            float2 h1b = *(const float2*)&hsb[(j0 + 1) * HSTR + rfin + 2];
            float hold0[4] = {h0a.x, h0a.y, h0b.x, h0b.y};
            float hold1[4] = {h1a.x, h1a.y, h1b.x, h1b.y};
            float hn0[4], hn1[4];
#pragma unroll
            for (int i = 0; i < 4; i++) {
                hn0[i] = (1.0f - zv0[i]) * hold0[i] + zv0[i] * pre0[i];
                hn1[i] = (1.0f - zv1[i]) * hold1[i] + zv1[i] * pre1[i];
            }
            *(ull*)&hsb[j0 * HSTR + rfin]           = pack2(hn0[0], hn0[1]);
            *(ull*)&hsb[j0 * HSTR + rfin + 2]       = pack2(hn0[2], hn0[3]);
            *(ull*)&hsb[(j0 + 1) * HSTR + rfin]     = pack2(hn1[0], hn1[1]);
            *(ull*)&hsb[(j0 + 1) * HSTR + rfin + 2] = pack2(hn1[2], hn1[3]);
#pragma unroll
            for (int i = 0; i < 4; i++) {
                int  row   = row0 + rfin + i;
                bool valid = (t < slenr[i]);
                int  base  = row * (Tk * OW) + t * OW;
                *(float2*)&out_all[base + j0] =
                    valid ? make_float2(hn0[i], hn1[i]) : make_float2(0.f, 0.f);
                *(float2*)&out_all[base + Hk + j0] =
                    valid ? latp[i] : make_float2(0.f, 0.f);
                if (valid) {
                    segj0[i] = fmaxf(segj0[i], hn0[i]);
                    segj1[i] = fmaxf(segj1[i], hn1[i]);
                }
                if (t == slenr[i] - 1)
                    *(float2*)&out_newh[row * Hk + j0] = make_float2(hn0[i], hn1[i]);
            }
        }
        wp = pwbase[0];   // prefetch next-t stage1 weights behind barrier
    }

#pragma unroll
    for (int i = 0; i < 4; i++) {
        int row = row0 + rfin + i;
        *(float2*)&out_seg[row * Hk + j0] = make_float2(segj0[i], segj1[i]);
    }
}

extern "C" void kernel_launch(void* const* d_in, const int* in_sizes, int n_in,
                              void* d_out, int out_size) {
    const float* x_seq   = (const float*)d_in[0];
    const float* hidden  = (const float*)d_in[1];
    const float* tree    = (const float*)d_in[2];
    const float* graph   = (const float*)d_in[3];
    const int*   lengths = (const int*)  d_in[4];
    const float* Wcs = (const float*)d_in[5];
    const float* bcs = (const float*)d_in[6];
    const float* Wz  = (const float*)d_in[7];
    const float* bz  = (const float*)d_in[8];
    const float* Wr  = (const float*)d_in[9];
    const float* br  = (const float*)d_in[10];
    const float* Wh  = (const float*)d_in[11];
    const float* bh  = (const float*)d_in[12];
    float* out = (float*)d_out;

    cudaFuncSetAttribute(gru_decoder_kernel,
                         cudaFuncAttributeMaxDynamicSharedMemorySize,
                         SMEM_F * (int)sizeof(float));
    repack_kernel<<<Hk * 128 / 256, 256>>>(Wz, Wr);
    gru_decoder_kernel<<<Bk / Rk, 512, SMEM_F * sizeof(float)>>>(
        x_seq, hidden, tree, graph, lengths,
        Wcs, bcs, Wz, bz, Wr, br, Wh, bh, out);
}

// round 14
// speedup vs baseline: 1.8779x; 1.8779x over previous
#include <cuda_runtime.h>
#include <cstdint>

#define Bk 2048
#define Tk 100
#define Hk 256
#define Lk 128
#define NVk 5
#define Rk 16
#define OW 512
#define HSTR 20     // hs/rh k-row stride in floats
#define ESTR 17     // pex entry stride in ull

#define RH_OFF   (Hk * HSTR)                 // 5120 floats
#define PEX_OFF  (2 * Hk * HSTR)             // 10240 floats
#define PEX_FL   (2 * 256 * ESTR)            // 8704 floats (as ull region)
#define XW_OFF   (PEX_OFF + PEX_FL)          // 18944
#define XW_FL    (3 * 6 * Hk)                // 4608 (x-weights + bias, 3 gates)
#define LAT_OFF  (XW_OFF + XW_FL)            // 23552
#define LAT_FL   (Rk * Hk)                   // 4096: latsm[r*256 + j]
#define XALL_OFF (LAT_OFF + LAT_FL)          // 27648
#define XALL_FL  (Tk * NVk * 16)             // 8000: xall[(t*5+v)*16 + r]
#define SMEM_F   (XALL_OFF + XALL_FL)        // 35648 floats = 142592 B

typedef unsigned long long ull;

// Pairwise barrier between kh-partner warps (w and w^8): ids 1..8, 64 threads.
#define PAIRBAR(bid) asm volatile("bar.sync %0, 64;" :: "r"(bid) : "memory")
// rh-scoped barrier: the 8 warps of one rh half (ids 9,10), 256 threads.
#define RHBAR(rhid)  asm volatile("bar.sync %0, 256;" :: "r"(9 + (rhid)) : "memory")

// Repacked stage-1 weights: g_wzr[k*Hk + j] = (wz, wr); float4 view gives
// (wz_j0, wr_j0, wz_j1, wr_j1) for a j-pair in one LDG.128.
__device__ __align__(16) float2 g_wzr[Hk * Hk];

__device__ __forceinline__ void fma2(ull& d, ull a, ull b) {
    asm("fma.rn.f32x2 %0, %1, %2, %0;" : "+l"(d) : "l"(a), "l"(b));
}
__device__ __forceinline__ void add2(ull& d, ull a) {
    asm("add.rn.f32x2 %0, %0, %1;" : "+l"(d) : "l"(a));
}
__device__ __forceinline__ ull pack2(float lo, float hi) {
    ull r; asm("mov.b64 %0, {%1, %2};" : "=l"(r) : "f"(lo), "f"(hi)); return r;
}
__device__ __forceinline__ float2 unpack2(ull p) {
    float2 f; asm("mov.b64 {%0, %1}, %2;" : "=f"(f.x), "=f"(f.y) : "l"(p)); return f;
}
__device__ __forceinline__ float sigmoidf_fast(float x) {
    return 1.0f / (1.0f + __expf(-x));
}
// volatile smem v2 load: keeps loop-invariant xw out of persistent registers.
__device__ __forceinline__ float2 lds2v(uint32_t a) {
    float2 f;
    asm volatile("ld.shared.v2.f32 {%0,%1},[%2];" : "=f"(f.x), "=f"(f.y) : "r"(a));
    return f;
}
__device__ __forceinline__ void fma8s(float acc[8], float4 a0, float4 a1, float wv) {
    acc[0] = fmaf(a0.x, wv, acc[0]); acc[1] = fmaf(a0.y, wv, acc[1]);
    acc[2] = fmaf(a0.z, wv, acc[2]); acc[3] = fmaf(a0.w, wv, acc[3]);
    acc[4] = fmaf(a1.x, wv, acc[4]); acc[5] = fmaf(a1.y, wv, acc[5]);
    acc[6] = fmaf(a1.z, wv, acc[6]); acc[7] = fmaf(a1.w, wv, acc[7]);
}

__global__ void repack_kernel(const float* __restrict__ Wz,
                              const float* __restrict__ Wr) {
    int idx = blockIdx.x * blockDim.x + threadIdx.x;
    int k = idx >> 8, j = idx & (Hk - 1);
    g_wzr[idx] = make_float2(Wz[(NVk + k) * Hk + j], Wr[(NVk + k) * Hk + j]);
}

// 128 blocks x 512 threads. Thread (jp, rh, kh): columns j0=2jp, j1=j0+1;
// accumulates rows [rh*8, rh*8+8) over k-half [kh*128, +128); finalizes
// rows rfin = rh*8 + kh*4 .. +4 after a 2-way partial exchange via smem.
__global__ __launch_bounds__(512, 1)
void gru_decoder_kernel(
    const float* __restrict__ x_seq,
    const float* __restrict__ hidden,
    const float* __restrict__ tree,
    const float* __restrict__ graph,
    const int*   __restrict__ lengths,
    const float* __restrict__ Wcs, const float* __restrict__ bcs,
    const float* __restrict__ Wz,  const float* __restrict__ bz,
    const float* __restrict__ Wr,  const float* __restrict__ br,
    const float* __restrict__ Wh,  const float* __restrict__ bh,
    float* __restrict__ out)
{
    extern __shared__ __align__(16) float smf[];
    float* hsb  = smf;                       // hs[k*HSTR + r]
    float* rhb  = smf + RH_OFF;              // rh[k*HSTR + r]
    ull*   pexu = (ull*)(smf + PEX_OFF);     // exchange buffer
    float* cvb  = smf + PEX_OFF;             // prologue overlay (6144 floats)
    float* xw   = smf + XW_OFF;              // x-weights+bias [g][v(6)][j]
    float* latsm= smf + LAT_OFF;             // latents [r][j] (reg relief)
    float* xall = smf + XALL_OFF;            // x preload [(t*5+v)*16 + r]

    const int tid  = threadIdx.x;
    const int jp   = tid & 127;
    const int rh   = (tid >> 7) & 1;
    const int kh   = tid >> 8;
    const int j0   = jp << 1;
    const int rbase = rh << 3;
    const int rfin  = rbase + (kh << 2);
    const int rexp  = rbase + ((1 - kh) << 2);
    const int ep    = (1 - kh) << 1;
    const int op    = kh << 1;
    const int k0    = kh << 7;
    const int row0  = blockIdx.x * Rk;
    const int pbid  = 1 + ((tid >> 5) & 7);

    float* out_newh = out;
    float* out_all  = out + Bk * Hk;
    float* out_seg  = out + Bk * Hk + Bk * Tk * OW;

    // ---- one-time loads ----
    for (int idx = tid; idx < XW_FL; idx += 512) {
        int g = idx / (6 * Hk);
        int vj = idx - g * 6 * Hk;
        int v = vj >> 8, j = vj & 255;
        const float* W = (g == 0) ? Wz : ((g == 1) ? Wr : Wh);
        const float* bb = (g == 0) ? bz : ((g == 1) ? br : bh);
        xw[idx] = (v < NVk) ? W[v * Hk + j] : bb[j];
    }
    for (int idx = tid; idx < Rk * Tk * NVk; idx += 512) {
        int r  = idx / (Tk * NVk);
        int tv = idx - r * (Tk * NVk);
        xall[tv * 16 + r] = x_seq[(row0 + r) * (Tk * NVk) + tv];
    }
    // latents to smem (frees 8 registers vs keeping them resident)
    for (int idx = tid; idx < LAT_FL; idx += 512) {
        int r = idx >> 8, j = idx & 255;
        latsm[idx] = (j < Lk) ? tree[(row0 + r) * Lk + j]
                              : graph[(row0 + r) * Lk + (j - Lk)];
    }

    int slenr[4];
#pragma unroll
    for (int i = 0; i < 4; i++) slenr[i] = lengths[row0 + rfin + i];

    for (int idx = tid; idx < Rk * (Hk + Lk); idx += 512) {
        int r = idx / (Hk + Lk);
        int k = idx - r * (Hk + Lk);
        cvb[k * 16 + r] = (k < Hk) ? hidden[(row0 + r) * Hk + k]
                                   : graph[(row0 + r) * Lk + (k - Hk)];
    }
    __syncthreads();

    // h0 = relu(cv @ Wcs + bcs)
    {
        const int jc   = tid & 255;
        const int orow = (tid >> 8) << 3;
        float acc[8];
        const float b0 = bcs[jc];
#pragma unroll
        for (int r = 0; r < 8; r++) acc[r] = b0;
        const float* pcs = Wcs + jc;
#pragma unroll 4
        for (int k = 0; k < Hk + Lk; k++) {
            float wv  = pcs[k * Hk];
            float4 a0 = *(const float4*)&cvb[k * 16 + orow];
            float4 a1 = *(const float4*)&cvb[k * 16 + orow + 4];
            fma8s(acc, a0, a1, wv);
        }
#pragma unroll
        for (int r = 0; r < 8; r++) hsb[jc * HSTR + orow + r] = fmaxf(acc[r], 0.0f);
    }
    __syncthreads();   // h0 writer mapping is kh-based: full sync once, pre-loop

    float segj0[4], segj1[4];
#pragma unroll
    for (int i = 0; i < 4; i++) { segj0[i] = -1e30f; segj1[i] = -1e30f; }

    const uint32_t smem_u32 = (uint32_t)__cvta_generic_to_shared(smf);
    const uint32_t xbase    = smem_u32 + (uint32_t)(XW_OFF + j0) * 4u;

    ull* pe = pexu + (rh * 128 + jp) * ESTR + (1 - kh) * 8;
    const ull* po = pexu + (rh * 128 + jp) * ESTR + kh * 8;

    const float4* pwbase  = reinterpret_cast<const float4*>(g_wzr) + (k0 << 7) + jp;
    const float2* pwhbase = reinterpret_cast<const float2*>(Wh + NVk * Hk) + (k0 << 7) + jp;

    float4 wp = pwbase[0];   // prefetch stage1 weights for t=0

    for (int t = 0; t < Tk; t++) {
        if (t) RHBAR(rh);

        const float* xp = xall + t * (NVk * 16) + rexp;

        // ---- stage 1: z & r partials (2 j x 8 rows over own k-half) ----
        ull az0[4], az1[4], ar0[4], ar1[4];
        {
            float2 bz2 = lds2v(xbase + 5u * 1024u);
            float2 br2 = lds2v(xbase + 6144u + 5u * 1024u);
            float vz0[4], vz1[4], vr0[4], vr1[4];
#pragma unroll
            for (int i = 0; i < 4; i++) {
                vz0[i] = bz2.x; vz1[i] = bz2.y; vr0[i] = br2.x; vr1[i] = br2.y;
            }
#pragma unroll
            for (int v = 0; v < NVk; v++) {
                float2 wz = lds2v(xbase + (unsigned)v * 1024u);
                float2 wr = lds2v(xbase + 6144u + (unsigned)v * 1024u);
#pragma unroll
                for (int i = 0; i < 4; i++) {
                    float xv = xp[v * 16 + i];
                    vz0[i] = fmaf(xv, wz.x, vz0[i]); vz1[i] = fmaf(xv, wz.y, vz1[i]);
                    vr0[i] = fmaf(xv, wr.x, vr0[i]); vr1[i] = fmaf(xv, wr.y, vr1[i]);
                }
            }
            az0[ep] = pack2(vz0[0], vz0[1]); az0[ep + 1] = pack2(vz0[2], vz0[3]);
            az1[ep] = pack2(vz1[0], vz1[1]); az1[ep + 1] = pack2(vz1[2], vz1[3]);
            ar0[ep] = pack2(vr0[0], vr0[1]); ar0[ep + 1] = pack2(vr0[2], vr0[3]);
            ar1[ep] = pack2(vr1[0], vr1[1]); ar1[ep + 1] = pack2(vr1[2], vr1[3]);
            az0[op] = 0; az0[op + 1] = 0; az1[op] = 0; az1[op + 1] = 0;
            ar0[op] = 0; ar0[op + 1] = 0; ar1[op] = 0; ar1[op + 1] = 0;
        }
        {
            const char* hp = (const char*)(hsb + k0 * HSTR + rbase);
            {   // peeled kk=0 with prefetched weights (LDG hidden behind barrier)
                ulonglong2 hA = *(const ulonglong2*)hp;
                ulonglong2 hB = *(const ulonglong2*)(hp + 16);
                hp += HSTR * 4;
                ull wzz0 = pack2(wp.x, wp.x), wrr0 = pack2(wp.y, wp.y);
                ull wzz1 = pack2(wp.z, wp.z), wrr1 = pack2(wp.w, wp.w);
                fma2(az0[0], hA.x, wzz0); fma2(az0[1], hA.y, wzz0);
                fma2(az0[2], hB.x, wzz0); fma2(az0[3], hB.y, wzz0);
                fma2(az1[0], hA.x, wzz1); fma2(az1[1], hA.y, wzz1);
                fma2(az1[2], hB.x, wzz1); fma2(az1[3], hB.y, wzz1);
                fma2(ar0[0], hA.x, wrr0); fma2(ar0[1], hA.y, wrr0);
                fma2(ar0[2], hB.x, wrr0); fma2(ar0[3], hB.y, wrr0);
                fma2(ar1[0], hA.x, wrr1); fma2(ar1[1], hA.y, wrr1);
                fma2(ar1[2], hB.x, wrr1); fma2(ar1[3], hB.y, wrr1);
            }
            const float4* pw = pwbase + 128;
#pragma unroll 8
            for (int kk = 1; kk < 128; kk++) {
                float4 w = *pw; pw += 128;
                ulonglong2 hA = *(const ulonglong2*)hp;
                ulonglong2 hB = *(const ulonglong2*)(hp + 16);
                hp += HSTR * 4;
                ull wzz0 = pack2(w.x, w.x), wrr0 = pack2(w.y, w.y);
                ull wzz1 = pack2(w.z, w.z), wrr1 = pack2(w.w, w.w);
                fma2(az0[0], hA.x, wzz0); fma2(az0[1], hA.y, wzz0);
                fma2(az0[2], hB.x, wzz0); fma2(az0[3], hB.y, wzz0);
                fma2(az1[0], hA.x, wzz1); fma2(az1[1], hA.y, wzz1);
                fma2(az1[2], hB.x, wzz1); fma2(az1[3], hB.y, wzz1);
                fma2(ar0[0], hA.x, wrr0); fma2(ar0[1], hA.y, wrr0);
                fma2(ar0[2], hB.x, wrr0); fma2(ar0[3], hB.y, wrr0);
                fma2(ar1[0], hA.x, wrr1); fma2(ar1[1], hA.y, wrr1);
                fma2(ar1[2], hB.x, wrr1); fma2(ar1[3], hB.y, wrr1);
            }
        }
        // export partner's 4 rows
        pe[0] = az0[ep]; pe[1] = az0[ep + 1]; pe[2] = az1[ep]; pe[3] = az1[ep + 1];
        pe[4] = ar0[ep]; pe[5] = ar0[ep + 1]; pe[6] = ar1[ep]; pe[7] = ar1[ep + 1];
        PAIRBAR(pbid);

        float zv0[4], zv1[4];
        {
            add2(az0[op], po[0]); add2(az0[op + 1], po[1]);
            add2(az1[op], po[2]); add2(az1[op + 1], po[3]);
            add2(ar0[op], po[4]); add2(ar0[op + 1], po[5]);
            add2(ar1[op], po[6]); add2(ar1[op + 1], po[7]);
            float2 z0a = unpack2(az0[op]), z0b = unpack2(az0[op + 1]);
            float2 z1a = unpack2(az1[op]), z1b = unpack2(az1[op + 1]);
            zv0[0] = sigmoidf_fast(z0a.x); zv0[1] = sigmoidf_fast(z0a.y);
            zv0[2] = sigmoidf_fast(z0b.x); zv0[3] = sigmoidf_fast(z0b.y);
            zv1[0] = sigmoidf_fast(z1a.x); zv1[1] = sigmoidf_fast(z1a.y);
            zv1[2] = sigmoidf_fast(z1b.x); zv1[3] = sigmoidf_fast(z1b.y);
            float2 r0a = unpack2(ar0[op]), r0b = unpack2(ar0[op + 1]);
            float2 r1a = unpack2(ar1[op]), r1b = unpack2(ar1[op + 1]);
            float2 h0a = *(const float2*)&hsb[j0 * HSTR + rfin];
            float2 h0b = *(const float2*)&hsb[j0 * HSTR + rfin + 2];
            float2 h1a = *(const float2*)&hsb[(j0 + 1) * HSTR + rfin];
            float2 h1b = *(const float2*)&hsb[(j0 + 1) * HSTR + rfin + 2];
            *(ull*)&rhb[j0 * HSTR + rfin] =
                pack2(sigmoidf_fast(r0a.x) * h0a.x, sigmoidf_fast(r0a.y) * h0a.y);
            *(ull*)&rhb[j0 * HSTR + rfin + 2] =
                pack2(sigmoidf_fast(r0b.x) * h0b.x, sigmoidf_fast(r0b.y) * h0b.y);
            *(ull*)&rhb[(j0 + 1) * HSTR + rfin] =
                pack2(sigmoidf_fast(r1a.x) * h1a.x, sigmoidf_fast(r1a.y) * h1a.y);
            *(ull*)&rhb[(j0 + 1) * HSTR + rfin + 2] =
                pack2(sigmoidf_fast(r1b.x) * h1b.x, sigmoidf_fast(r1b.y) * h1b.y);
        }

        // ---- stage 2 x-part init (rhb-independent; before rh barrier) ----
        ull ah0[4], ah1[4];
        {
            float2 bh2 = lds2v(xbase + 12288u + 5u * 1024u);
            float vh0[4], vh1[4];
#pragma unroll
            for (int i = 0; i < 4; i++) { vh0[i] = bh2.x; vh1[i] = bh2.y; }
#pragma unroll
            for (int v = 0; v < NVk; v++) {
                float2 wh = lds2v(xbase + 12288u + (unsigned)v * 1024u);
#pragma unroll
                for (int i = 0; i < 4; i++) {
                    float xv = xp[v * 16 + i];
                    vh0[i] = fmaf(xv, wh.x, vh0[i]); vh1[i] = fmaf(xv, wh.y, vh1[i]);
                }
            }
            ah0[ep] = pack2(vh0[0], vh0[1]); ah0[ep + 1] = pack2(vh0[2], vh0[3]);
            ah1[ep] = pack2(vh1[0], vh1[1]); ah1[ep + 1] = pack2(vh1[2], vh1[3]);
            ah0[op] = 0; ah0[op + 1] = 0; ah1[op] = 0; ah1[op + 1] = 0;
        }
        float2 whp = pwhbase[0];
        RHBAR(rh);

        {
            const char* rp = (const char*)(rhb + k0 * HSTR + rbase);
            {   // peeled kk=0
                ulonglong2 rA = *(const ulonglong2*)rp;
                ulonglong2 rB = *(const ulonglong2*)(rp + 16);
                rp += HSTR * 4;
                ull whh0 = pack2(whp.x, whp.x), whh1 = pack2(whp.y, whp.y);
                fma2(ah0[0], rA.x, whh0); fma2(ah0[1], rA.y, whh0);
                fma2(ah0[2], rB.x, whh0); fma2(ah0[3], rB.y, whh0);
                fma2(ah1[0], rA.x, whh1); fma2(ah1[1], rA.y, whh1);
                fma2(ah1[2], rB.x, whh1); fma2(ah1[3], rB.y, whh1);
            }
            const float2* pwh = pwhbase + 128;
#pragma unroll 8
            for (int kk = 1; kk < 128; kk++) {
                float2 wh = *pwh; pwh += 128;
                ulonglong2 rA = *(const ulonglong2*)rp;
                ulonglong2 rB = *(const ulonglong2*)(rp + 16);
                rp += HSTR * 4;
                ull whh0 = pack2(wh.x, wh.x), whh1 = pack2(wh.y, wh.y);
                fma2(ah0[0], rA.x, whh0); fma2(ah0[1], rA.y, whh0);
                fma2(ah0[2], rB.x, whh0); fma2(ah0[3], rB.y, whh0);
                fma2(ah1[0], rA.x, whh1); fma2(ah1[1], rA.y, whh1);
                fma2(ah1[2], rB.x, whh1); fma2(ah1[3], rB.y, whh1);
            }
        }
        pe[0] = ah0[ep]; pe[1] = ah0[ep + 1]; pe[2] = ah1[ep]; pe[3] = ah1[ep + 1];
        PAIRBAR(pbid);

        // ---- combine + epilogue for own 2j x 4 rows ----
        {
            add2(ah0[op], po[0]); add2(ah0[op + 1], po[1]);
            add2(ah1[op], po[2]); add2(ah1[op + 1], po[3]);
            float2 p0a = unpack2(ah0[op]), p0b = unpack2(ah0[op + 1]);
            float2 p1a = unpack2(ah1[op]), p1b = unpack2(ah1[op + 1]);
            float pre0[4] = {tanhf(p0a.x), tanhf(p0a.y), tanhf(p0b.x), tanhf(p0b.y)};
            float pre1[4] = {tanhf(p1a.x), tanhf(p1a.y), tanhf(p1b.x), tanhf(p1b.y)};
            float2 h0a = *(const float2*)&hsb[j0 * HSTR + rfin];
            float2 h0b = *(const float2*)&hsb[j0 * HSTR + rfin + 2];
            float2 h1a = *(const float2*)&hsb[(j0 + 1) * HSTR + rfin];
            float2 h1b = *(const float2*)&hsb[(j0 + 1) * HSTR + rfin + 2];
            float hold0[4] = {h0a.x, h0a.y, h0b.x, h0b.y};
            float hold1[4] = {h1a.x, h1a.y, h1b.x, h1b.y};
            float hn0[4], hn1[4];
#pragma unroll
            for (int i = 0; i < 4; i++) {
                hn0[i] = (1.0f - zv0[i]) * hold0[i] + zv0[i] * pre0[i];
                hn1[i] = (1.0f - zv1[i]) * hold1[i] + zv1[i] * pre1[i];
            }
            *(ull*)&hsb[j0 * HSTR + rfin]           = pack2(hn0[0], hn0[1]);
            *(ull*)&hsb[j0 * HSTR + rfin + 2]       = pack2(hn0[2], hn0[3]);
            *(ull*)&hsb[(j0 + 1) * HSTR + rfin]     = pack2(hn1[0], hn1[1]);
            *(ull*)&hsb[(j0 + 1) * HSTR + rfin + 2] = pack2(hn1[2], hn1[3]);
#pragma unroll
            for (int i = 0; i < 4; i++) {
                int  row   = row0 + rfin + i;
                bool valid = (t < slenr[i]);
                int  base  = row * (Tk * OW) + t * OW;
                float2 latv = *(const float2*)&latsm[(rfin + i) * Hk + j0];
                *(float2*)&out_all[base + j0] =
                    valid ? make_float2(hn0[i], hn1[i]) : make_float2(0.f, 0.f);
                *(float2*)&out_all[base + Hk + j0] =
                    valid ? latv : make_float2(0.f, 0.f);
                if (valid) {
                    segj0[i] = fmaxf(segj0[i], hn0[i]);
                    segj1[i] = fmaxf(segj1[i], hn1[i]);
                }
                if (t == slenr[i] - 1)
                    *(float2*)&out_newh[row * Hk + j0] = make_float2(hn0[i], hn1[i]);
            }
        }
        wp = pwbase[0];   // prefetch next-t stage1 weights behind barrier
    }

#pragma unroll
    for (int i = 0; i < 4; i++) {
        int row = row0 + rfin + i;
        *(float2*)&out_seg[row * Hk + j0] = make_float2(segj0[i], segj1[i]);
    }
}

extern "C" void kernel_launch(void* const* d_in, const int* in_sizes, int n_in,
                              void* d_out, int out_size) {
    const float* x_seq   = (const float*)d_in[0];
    const float* hidden  = (const float*)d_in[1];
    const float* tree    = (const float*)d_in[2];
    const float* graph   = (const float*)d_in[3];
    const int*   lengths = (const int*)  d_in[4];
    const float* Wcs = (const float*)d_in[5];
    const float* bcs = (const float*)d_in[6];
    const float* Wz  = (const float*)d_in[7];
    const float* bz  = (const float*)d_in[8];
    const float* Wr  = (const float*)d_in[9];
    const float* br  = (const float*)d_in[10];
    const float* Wh  = (const float*)d_in[11];
    const float* bh  = (const float*)d_in[12];
    float* out = (float*)d_out;

    cudaFuncSetAttribute(gru_decoder_kernel,
                         cudaFuncAttributeMaxDynamicSharedMemorySize,
                         SMEM_F * (int)sizeof(float));
    repack_kernel<<<Hk * Hk / 256, 256>>>(Wz, Wr);
    gru_decoder_kernel<<<Bk / Rk, 512, SMEM_F * sizeof(float)>>>(
        x_seq, hidden, tree, graph, lengths,
        Wcs, bcs, Wz, bz, Wr, br, Wh, bh, out);
}

// round 15
// speedup vs baseline: 2.2946x; 1.2219x over previous
#include <cuda_runtime.h>
#include <cstdint>

#define Bk 2048
#define Tk 100
#define Hk 256
#define Lk 128
#define NVk 5
#define Rk 8        // batch rows per block
#define OW 512
#define HSTR 12     // hs/rh k-row stride in floats (48B)
#define ESTR 17     // pex entry stride in ull

#define RH_OFF   (Hk * HSTR)                 // 3072 floats
#define PEX_OFF  (2 * Hk * HSTR)             // 6144 floats
#define PEX_FL   (128 * ESTR * 2)            // 4352 floats (2176 ull)
#define XW_OFF   (PEX_OFF + PEX_FL)          // 10496
#define XW_FL    (3 * 6 * Hk)                // 4608
#define LAT_OFF  (XW_OFF + XW_FL)            // 15104
#define LAT_FL   (Rk * Hk)                   // 2048
#define XALL_OFF (LAT_OFF + LAT_FL)          // 17152
#define XALL_FL  (Tk * NVk * Rk)             // 4000
#define SMEM_F   (XALL_OFF + XALL_FL)        // 21152 floats = 84608 B (2 blocks/SM)

typedef unsigned long long ull;

// Pairwise barrier between kh-partner warps (w and w^4): ids 1..4, 64 threads.
#define PAIRBAR(bid) asm volatile("bar.sync %0, 64;" :: "r"(bid) : "memory")

// Repacked stage-1 weights: g_wzr[k*Hk + j] = (wz, wr); float4 view gives
// (wz_j0, wr_j0, wz_j1, wr_j1) for a j-pair in one LDG.128.
__device__ __align__(16) float2 g_wzr[Hk * Hk];
// Row permutation: rows sorted by length DESCENDING (deterministic rank sort).
__device__ int g_perm[Bk];

__device__ __forceinline__ void fma2(ull& d, ull a, ull b) {
    asm("fma.rn.f32x2 %0, %1, %2, %0;" : "+l"(d) : "l"(a), "l"(b));
}
__device__ __forceinline__ void add2(ull& d, ull a) {
    asm("add.rn.f32x2 %0, %0, %1;" : "+l"(d) : "l"(a));
}
__device__ __forceinline__ ull pack2(float lo, float hi) {
    ull r; asm("mov.b64 %0, {%1, %2};" : "=l"(r) : "f"(lo), "f"(hi)); return r;
}
__device__ __forceinline__ float2 unpack2(ull p) {
    float2 f; asm("mov.b64 {%0, %1}, %2;" : "=f"(f.x), "=f"(f.y) : "l"(p)); return f;
}
__device__ __forceinline__ float sigmoidf_fast(float x) {
    return 1.0f / (1.0f + __expf(-x));
}
__device__ __forceinline__ float2 lds2v(uint32_t a) {
    float2 f;
    asm volatile("ld.shared.v2.f32 {%0,%1},[%2];" : "=f"(f.x), "=f"(f.y) : "r"(a));
    return f;
}
__device__ __forceinline__ void fma8s(float acc[8], float4 a0, float4 a1, float wv) {
    acc[0] = fmaf(a0.x, wv, acc[0]); acc[1] = fmaf(a0.y, wv, acc[1]);
    acc[2] = fmaf(a0.z, wv, acc[2]); acc[3] = fmaf(a0.w, wv, acc[3]);
    acc[4] = fmaf(a1.x, wv, acc[4]); acc[5] = fmaf(a1.y, wv, acc[5]);
    acc[6] = fmaf(a1.z, wv, acc[6]); acc[7] = fmaf(a1.w, wv, acc[7]);
}

__global__ void repack_kernel(const float* __restrict__ Wz,
                              const float* __restrict__ Wr) {
    int idx = blockIdx.x * blockDim.x + threadIdx.x;
    int k = idx >> 8, j = idx & (Hk - 1);
    g_wzr[idx] = make_float2(Wz[(NVk + k) * Hk + j], Wr[(NVk + k) * Hk + j]);
}

// Deterministic rank sort (descending by length, ties by index).
__global__ void rank_kernel(const int* __restrict__ lengths) {
    __shared__ int lens[Bk];
    for (int i = threadIdx.x; i < Bk; i += 1024) lens[i] = lengths[i];
    __syncthreads();
    for (int i = threadIdx.x; i < Bk; i += 1024) {
        int li = lens[i];
        int rank = 0;
        for (int j = 0; j < Bk; j++) {
            int lj = lens[j];
            rank += (lj > li) || (lj == li && j < i);
        }
        g_perm[rank] = i;
    }
}

// 256 blocks x 256 threads, 2 co-resident blocks/SM. Block b owns rows
// perm[8b..8b+8] (length-sorted, descending => LPT scheduling). Runs only
// tmax = max(len in group) GRU steps, then zero-fills the padded tail.
// Thread (jp, kh): columns j0=2jp, j1=j0+1; accumulates 8 rows over k-half
// [kh*128, +128); finalizes rows rfin = kh*4..+4 after pairwise exchange.
__global__ __launch_bounds__(256, 2)
void gru_decoder_kernel(
    const float* __restrict__ x_seq,
    const float* __restrict__ hidden,
    const float* __restrict__ tree,
    const float* __restrict__ graph,
    const int*   __restrict__ lengths,
    const float* __restrict__ Wcs, const float* __restrict__ bcs,
    const float* __restrict__ Wz,  const float* __restrict__ bz,
    const float* __restrict__ Wr,  const float* __restrict__ br,
    const float* __restrict__ Wh,  const float* __restrict__ bh,
    float* __restrict__ out)
{
    extern __shared__ __align__(16) float smf[];
    float* hsb  = smf;                       // hs[k*HSTR + r]
    float* rhb  = smf + RH_OFF;              // rh[k*HSTR + r]
    ull*   pexu = (ull*)(smf + PEX_OFF);     // exchange buffer
    float* cvb  = smf + PEX_OFF;             // prologue overlay (3072 floats)
    float* xw   = smf + XW_OFF;              // x-weights+bias [g][v(6)][j]
    float* latsm= smf + LAT_OFF;             // latents [r][j]
    float* xall = smf + XALL_OFF;            // x preload [(t*5+v)*8 + r]

    __shared__ int rowsm[Rk];                // permuted absolute row ids
    __shared__ int slensm[Rk];

    const int tid  = threadIdx.x;
    const int jp   = tid & 127;
    const int kh   = tid >> 7;
    const int j0   = jp << 1;
    const int rfin = kh << 2;
    const int rexp = (1 - kh) << 2;
    const int ep   = (1 - kh) << 1;
    const int op   = kh << 1;
    const int k0   = kh << 7;
    const int pbid = 1 + ((tid >> 5) & 3);

    float* out_newh = out;
    float* out_all  = out + Bk * Hk;
    float* out_seg  = out + Bk * Hk + Bk * Tk * OW;

    // ---- group rows via permutation ----
    if (tid < Rk) {
        int row = g_perm[blockIdx.x * Rk + tid];
        rowsm[tid]  = row;
        slensm[tid] = lengths[row];
    }
    __syncthreads();

    int rowr[4], slenr[4];
#pragma unroll
    for (int i = 0; i < 4; i++) {
        rowr[i]  = rowsm[rfin + i];
        slenr[i] = slensm[rfin + i];
    }
    int tmax = slensm[0];
#pragma unroll
    for (int r = 1; r < Rk; r++) tmax = max(tmax, slensm[r]);

    // ---- one-time loads ----
    for (int idx = tid; idx < XW_FL; idx += 256) {
        int g = idx / (6 * Hk);
        int vj = idx - g * 6 * Hk;
        int v = vj >> 8, j = vj & 255;
        const float* W = (g == 0) ? Wz : ((g == 1) ? Wr : Wh);
        const float* bb = (g == 0) ? bz : ((g == 1) ? br : bh);
        xw[idx] = (v < NVk) ? W[v * Hk + j] : bb[j];
    }
    for (int idx = tid; idx < Rk * Tk * NVk; idx += 256) {
        int r  = idx / (Tk * NVk);
        int tv = idx - r * (Tk * NVk);
        xall[tv * Rk + r] = x_seq[rowsm[r] * (Tk * NVk) + tv];
    }
    for (int idx = tid; idx < LAT_FL; idx += 256) {
        int r = idx >> 8, j = idx & 255;
        latsm[idx] = (j < Lk) ? tree[rowsm[r] * Lk + j]
                              : graph[rowsm[r] * Lk + (j - Lk)];
    }
    for (int idx = tid; idx < Rk * (Hk + Lk); idx += 256) {
        int r = idx / (Hk + Lk);
        int k = idx - r * (Hk + Lk);
        cvb[k * Rk + r] = (k < Hk) ? hidden[rowsm[r] * Hk + k]
                                   : graph[rowsm[r] * Lk + (k - Hk)];
    }
    __syncthreads();

    // h0 = relu(cv @ Wcs + bcs): thread covers column jc = tid, 8 rows
    {
        const int jc = tid;
        float acc[8];
        const float b0 = bcs[jc];
#pragma unroll
        for (int r = 0; r < 8; r++) acc[r] = b0;
        const float* pcs = Wcs + jc;
#pragma unroll 4
        for (int k = 0; k < Hk + Lk; k++) {
            float wv  = pcs[k * Hk];
            float4 a0 = *(const float4*)&cvb[k * Rk];
            float4 a1 = *(const float4*)&cvb[k * Rk + 4];
            fma8s(acc, a0, a1, wv);
        }
#pragma unroll
        for (int r = 0; r < 8; r++) hsb[jc * HSTR + r] = fmaxf(acc[r], 0.0f);
    }

    float segj0[4], segj1[4];
#pragma unroll
    for (int i = 0; i < 4; i++) { segj0[i] = -1e30f; segj1[i] = -1e30f; }

    const uint32_t smem_u32 = (uint32_t)__cvta_generic_to_shared(smf);
    const uint32_t xbase    = smem_u32 + (uint32_t)(XW_OFF + j0) * 4u;

    ull* pe = pexu + jp * ESTR + (1 - kh) * 8;
    const ull* po = pexu + jp * ESTR + kh * 8;

    const float4* pwbase  = reinterpret_cast<const float4*>(g_wzr) + (k0 << 7) + jp;
    const float2* pwhbase = reinterpret_cast<const float2*>(Wh + NVk * Hk) + (k0 << 7) + jp;

    float4 wp = pwbase[0];   // prefetch stage1 weights for t=0

    for (int t = 0; t < tmax; t++) {
        __syncthreads();   // prev-step hsb writes complete; pex reusable

        const float* xp = xall + t * (NVk * Rk) + rexp;

        // ---- stage 1: z & r partials (2 j x 8 rows over own k-half) ----
        ull az0[4], az1[4], ar0[4], ar1[4];
        {
            float2 bz2 = lds2v(xbase + 5u * 1024u);
            float2 br2 = lds2v(xbase + 6144u + 5u * 1024u);
            float vz0[4], vz1[4], vr0[4], vr1[4];
#pragma unroll
            for (int i = 0; i < 4; i++) {
                vz0[i] = bz2.x; vz1[i] = bz2.y; vr0[i] = br2.x; vr1[i] = br2.y;
            }
#pragma unroll
            for (int v = 0; v < NVk; v++) {
                float2 wz = lds2v(xbase + (unsigned)v * 1024u);
                float2 wr = lds2v(xbase + 6144u + (unsigned)v * 1024u);
#pragma unroll
                for (int i = 0; i < 4; i++) {
                    float xv = xp[v * Rk + i];
                    vz0[i] = fmaf(xv, wz.x, vz0[i]); vz1[i] = fmaf(xv, wz.y, vz1[i]);
                    vr0[i] = fmaf(xv, wr.x, vr0[i]); vr1[i] = fmaf(xv, wr.y, vr1[i]);
                }
            }
            az0[ep] = pack2(vz0[0], vz0[1]); az0[ep + 1] = pack2(vz0[2], vz0[3]);
            az1[ep] = pack2(vz1[0], vz1[1]); az1[ep + 1] = pack2(vz1[2], vz1[3]);
            ar0[ep] = pack2(vr0[0], vr0[1]); ar0[ep + 1] = pack2(vr0[2], vr0[3]);
            ar1[ep] = pack2(vr1[0], vr1[1]); ar1[ep + 1] = pack2(vr1[2], vr1[3]);
            az0[op] = 0; az0[op + 1] = 0; az1[op] = 0; az1[op + 1] = 0;
            ar0[op] = 0; ar0[op + 1] = 0; ar1[op] = 0; ar1[op + 1] = 0;
        }
        {
            const char* hp = (const char*)(hsb + k0 * HSTR);
            {   // peeled kk=0 with prefetched weights
                ulonglong2 hA = *(const ulonglong2*)hp;
                ulonglong2 hB = *(const ulonglong2*)(hp + 16);
                hp += HSTR * 4;
                ull wzz0 = pack2(wp.x, wp.x), wrr0 = pack2(wp.y, wp.y);
                ull wzz1 = pack2(wp.z, wp.z), wrr1 = pack2(wp.w, wp.w);
                fma2(az0[0], hA.x, wzz0); fma2(az0[1], hA.y, wzz0);
                fma2(az0[2], hB.x, wzz0); fma2(az0[3], hB.y, wzz0);
                fma2(az1[0], hA.x, wzz1); fma2(az1[1], hA.y, wzz1);
                fma2(az1[2], hB.x, wzz1); fma2(az1[3], hB.y, wzz1);
                fma2(ar0[0], hA.x, wrr0); fma2(ar0[1], hA.y, wrr0);
                fma2(ar0[2], hB.x, wrr0); fma2(ar0[3], hB.y, wrr0);
                fma2(ar1[0], hA.x, wrr1); fma2(ar1[1], hA.y, wrr1);
                fma2(ar1[2], hB.x, wrr1); fma2(ar1[3], hB.y, wrr1);
            }
            const float4* pw = pwbase + 128;
#pragma unroll 8
            for (int kk = 1; kk < 128; kk++) {
                float4 w = *pw; pw += 128;
                ulonglong2 hA = *(const ulonglong2*)hp;
                ulonglong2 hB = *(const ulonglong2*)(hp + 16);
                hp += HSTR * 4;
                ull wzz0 = pack2(w.x, w.x), wrr0 = pack2(w.y, w.y);
                ull wzz1 = pack2(w.z, w.z), wrr1 = pack2(w.w, w.w);
                fma2(az0[0], hA.x, wzz0); fma2(az0[1], hA.y, wzz0);
                fma2(az0[2], hB.x, wzz0); fma2(az0[3], hB.y, wzz0);
                fma2(az1[0], hA.x, wzz1); fma2(az1[1], hA.y, wzz1);
                fma2(az1[2], hB.x, wzz1); fma2(az1[3], hB.y, wzz1);
                fma2(ar0[0], hA.x, wrr0); fma2(ar0[1], hA.y, wrr0);
                fma2(ar0[2], hB.x, wrr0); fma2(ar0[3], hB.y, wrr0);
                fma2(ar1[0], hA.x, wrr1); fma2(ar1[1], hA.y, wrr1);
                fma2(ar1[2], hB.x, wrr1); fma2(ar1[3], hB.y, wrr1);
            }
        }
        pe[0] = az0[ep]; pe[1] = az0[ep + 1]; pe[2] = az1[ep]; pe[3] = az1[ep + 1];
        pe[4] = ar0[ep]; pe[5] = ar0[ep + 1]; pe[6] = ar1[ep]; pe[7] = ar1[ep + 1];
        PAIRBAR(pbid);

        float zv0[4], zv1[4];
        {
            add2(az0[op], po[0]); add2(az0[op + 1], po[1]);
            add2(az1[op], po[2]); add2(az1[op + 1], po[3]);
            add2(ar0[op], po[4]); add2(ar0[op + 1], po[5]);
            add2(ar1[op], po[6]); add2(ar1[op + 1], po[7]);
            float2 z0a = unpack2(az0[op]), z0b = unpack2(az0[op + 1]);
            float2 z1a = unpack2(az1[op]), z1b = unpack2(az1[op + 1]);
            zv0[0] = sigmoidf_fast(z0a.x); zv0[1] = sigmoidf_fast(z0a.y);
            zv0[2] = sigmoidf_fast(z0b.x); zv0[3] = sigmoidf_fast(z0b.y);
            zv1[0] = sigmoidf_fast(z1a.x); zv1[1] = sigmoidf_fast(z1a.y);
            zv1[2] = sigmoidf_fast(z1b.x); zv1[3] = sigmoidf_fast(z1b.y);
            float2 r0a = unpack2(ar0[op]), r0b = unpack2(ar0[op + 1]);
            float2 r1a = unpack2(ar1[op]), r1b = unpack2(ar1[op + 1]);
            float2 h0a = *(const float2*)&hsb[j0 * HSTR + rfin];
            float2 h0b = *(const float2*)&hsb[j0 * HSTR + rfin + 2];
            float2 h1a = *(const float2*)&hsb[(j0 + 1) * HSTR + rfin];
            float2 h1b = *(const float2*)&hsb[(j0 + 1) * HSTR + rfin + 2];
            *(ull*)&rhb[j0 * HSTR + rfin] =
                pack2(sigmoidf_fast(r0a.x) * h0a.x, sigmoidf_fast(r0a.y) * h0a.y);
            *(ull*)&rhb[j0 * HSTR + rfin + 2] =
                pack2(sigmoidf_fast(r0b.x) * h0b.x, sigmoidf_fast(r0b.y) * h0b.y);
            *(ull*)&rhb[(j0 + 1) * HSTR + rfin] =
                pack2(sigmoidf_fast(r1a.x) * h1a.x, sigmoidf_fast(r1a.y) * h1a.y);
            *(ull*)&rhb[(j0 + 1) * HSTR + rfin + 2] =
                pack2(sigmoidf_fast(r1b.x) * h1b.x, sigmoidf_fast(r1b.y) * h1b.y);
        }

        // ---- stage 2 x-part init (rhb-independent; before full sync) ----
        ull ah0[4], ah1[4];
        {
            float2 bh2 = lds2v(xbase + 12288u + 5u * 1024u);
            float vh0[4], vh1[4];
#pragma unroll
            for (int i = 0; i < 4; i++) { vh0[i] = bh2.x; vh1[i] = bh2.y; }
#pragma unroll
            for (int v = 0; v < NVk; v++) {
                float2 wh = lds2v(xbase + 12288u + (unsigned)v * 1024u);
#pragma unroll
                for (int i = 0; i < 4; i++) {
                    float xv = xp[v * Rk + i];
                    vh0[i] = fmaf(xv, wh.x, vh0[i]); vh1[i] = fmaf(xv, wh.y, vh1[i]);
                }
            }
            ah0[ep] = pack2(vh0[0], vh0[1]); ah0[ep + 1] = pack2(vh0[2], vh0[3]);
            ah1[ep] = pack2(vh1[0], vh1[1]); ah1[ep + 1] = pack2(vh1[2], vh1[3]);
            ah0[op] = 0; ah0[op + 1] = 0; ah1[op] = 0; ah1[op + 1] = 0;
        }
        float2 whp = pwhbase[0];   // prefetch stage2 weights behind barrier
        __syncthreads();           // rhb writes complete

        {
            const char* rp = (const char*)(rhb + k0 * HSTR);
            {   // peeled kk=0
                ulonglong2 rA = *(const ulonglong2*)rp;
                ulonglong2 rB = *(const ulonglong2*)(rp + 16);
                rp += HSTR * 4;
                ull whh0 = pack2(whp.x, whp.x), whh1 = pack2(whp.y, whp.y);
                fma2(ah0[0], rA.x, whh0); fma2(ah0[1], rA.y, whh0);
                fma2(ah0[2], rB.x, whh0); fma2(ah0[3], rB.y, whh0);
                fma2(ah1[0], rA.x, whh1); fma2(ah1[1], rA.y, whh1);
                fma2(ah1[2], rB.x, whh1); fma2(ah1[3], rB.y, whh1);
            }
            const float2* pwh = pwhbase + 128;
#pragma unroll 8
            for (int kk = 1; kk < 128; kk++) {
                float2 wh = *pwh; pwh += 128;
                ulonglong2 rA = *(const ulonglong2*)rp;
                ulonglong2 rB = *(const ulonglong2*)(rp + 16);
                rp += HSTR * 4;
                ull whh0 = pack2(wh.x, wh.x), whh1 = pack2(wh.y, wh.y);
                fma2(ah0[0], rA.x, whh0); fma2(ah0[1], rA.y, whh0);
                fma2(ah0[2], rB.x, whh0); fma2(ah0[3], rB.y, whh0);
                fma2(ah1[0], rA.x, whh1); fma2(ah1[1], rA.y, whh1);
                fma2(ah1[2], rB.x, whh1); fma2(ah1[3], rB.y, whh1);
            }
        }
        pe[0] = ah0[ep]; pe[1] = ah0[ep + 1]; pe[2] = ah1[ep]; pe[3] = ah1[ep + 1];
        PAIRBAR(pbid);

        // ---- combine + epilogue for own 2j x 4 rows ----
        {
            add2(ah0[op], po[0]); add2(ah0[op + 1], po[1]);
            add2(ah1[op], po[2]); add2(ah1[op + 1], po[3]);
            float2 p0a = unpack2(ah0[op]), p0b = unpack2(ah0[op + 1]);
            float2 p1a = unpack2(ah1[op]), p1b = unpack2(ah1[op + 1]);
            float pre0[4] = {tanhf(p0a.x), tanhf(p0a.y), tanhf(p0b.x), tanhf(p0b.y)};
            float pre1[4] = {tanhf(p1a.x), tanhf(p1a.y), tanhf(p1b.x), tanhf(p1b.y)};
            float2 h0a = *(const float2*)&hsb[j0 * HSTR + rfin];
            float2 h0b = *(const float2*)&hsb[j0 * HSTR + rfin + 2];
            float2 h1a = *(const float2*)&hsb[(j0 + 1) * HSTR + rfin];
            float2 h1b = *(const float2*)&hsb[(j0 + 1) * HSTR + rfin + 2];
            float hold0[4] = {h0a.x, h0a.y, h0b.x, h0b.y};
            float hold1[4] = {h1a.x, h1a.y, h1b.x, h1b.y};
            float hn0[4], hn1[4];
#pragma unroll
            for (int i = 0; i < 4; i++) {
                hn0[i] = (1.0f - zv0[i]) * hold0[i] + zv0[i] * pre0[i];
                hn1[i] = (1.0f - zv1[i]) * hold1[i] + zv1[i] * pre1[i];
            }
            *(ull*)&hsb[j0 * HSTR + rfin]           = pack2(hn0[0], hn0[1]);
            *(ull*)&hsb[j0 * HSTR + rfin + 2]       = pack2(hn0[2], hn0[3]);
            *(ull*)&hsb[(j0 + 1) * HSTR + rfin]     = pack2(hn1[0], hn1[1]);
            *(ull*)&hsb[(j0 + 1) * HSTR + rfin + 2] = pack2(hn1[2], hn1[3]);
#pragma unroll
            for (int i = 0; i < 4; i++) {
                int  row   = rowr[i];
                bool valid = (t < slenr[i]);
                int  base  = row * (Tk * OW) + t * OW;
                float2 latv = *(const float2*)&latsm[(rfin + i) * Hk + j0];
                *(float2*)&out_all[base + j0] =
                    valid ? make_float2(hn0[i], hn1[i]) : make_float2(0.f, 0.f);
                *(float2*)&out_all[base + Hk + j0] =
                    valid ? latv : make_float2(0.f, 0.f);
                if (valid) {
                    segj0[i] = fmaxf(segj0[i], hn0[i]);
                    segj1[i] = fmaxf(segj1[i], hn1[i]);
                }
                if (t == slenr[i] - 1)
                    *(float2*)&out_newh[row * Hk + j0] = make_float2(hn0[i], hn1[i]);
            }
        }
        wp = pwbase[0];   // prefetch next-t stage1 weights behind barrier
    }

    // ---- zero-fill padded tail t in [tmax, Tk) (pure stores) ----
    const float2 z2 = make_float2(0.f, 0.f);
    for (int t = tmax; t < Tk; t++) {
#pragma unroll
        for (int i = 0; i < 4; i++) {
            int base = rowr[i] * (Tk * OW) + t * OW;
            *(float2*)&out_all[base + j0]      = z2;
            *(float2*)&out_all[base + Hk + j0] = z2;
        }
    }

#pragma unroll
    for (int i = 0; i < 4; i++)
        *(float2*)&out_seg[rowr[i] * Hk + j0] = make_float2(segj0[i], segj1[i]);
}

extern "C" void kernel_launch(void* const* d_in, const int* in_sizes, int n_in,
                              void* d_out, int out_size) {
    const float* x_seq   = (const float*)d_in[0];
    const float* hidden  = (const float*)d_in[1];
    const float* tree    = (const float*)d_in[2];
    const float* graph   = (const float*)d_in[3];
    const int*   lengths = (const int*)  d_in[4];
    const float* Wcs = (const float*)d_in[5];
    const float* bcs = (const float*)d_in[6];
    const float* Wz  = (const float*)d_in[7];
    const float* bz  = (const float*)d_in[8];
    const float* Wr  = (const float*)d_in[9];
    const float* br  = (const float*)d_in[10];
    const float* Wh  = (const float*)d_in[11];
    const float* bh  = (const float*)d_in[12];
    float* out = (float*)d_out;

    cudaFuncSetAttribute(gru_decoder_kernel,
                         cudaFuncAttributeMaxDynamicSharedMemorySize,
                         SMEM_F * (int)sizeof(float));
    rank_kernel<<<1, 1024>>>(lengths);
    repack_kernel<<<Hk * Hk / 256, 256>>>(Wz, Wr);
    gru_decoder_kernel<<<Bk / Rk, 256, SMEM_F * sizeof(float)>>>(
        x_seq, hidden, tree, graph, lengths,
        Wcs, bcs, Wz, bz, Wr, br, Wh, bh, out);
}

// round 16
// speedup vs baseline: 2.4166x; 1.0532x over previous
#include <cuda_runtime.h>
#include <cstdint>

#define Bk 2048
#define Tk 100
#define Hk 256
#define Lk 128
#define NVk 5
#define Rk 8        // batch rows per block
#define OW 512
#define HSTR 12     // hs/rh k-row stride in floats (48B)
#define ESTR 17     // pex entry stride in ull

#define RH_OFF   (Hk * HSTR)                 // 3072 floats
#define PEX_OFF  (2 * Hk * HSTR)             // 6144 floats
#define PEX_FL   (128 * ESTR * 2)            // 4352 floats (2176 ull)
#define XW_OFF   (PEX_OFF + PEX_FL)          // 10496
#define XW_FL    (3 * 6 * Hk)                // 4608
#define LAT_OFF  (XW_OFF + XW_FL)            // 15104
#define LAT_FL   (Rk * Hk)                   // 2048
#define XALL_OFF (LAT_OFF + LAT_FL)          // 17152
#define XALL_FL  (Tk * NVk * Rk)             // 4000
#define SMEM_F   (XALL_OFF + XALL_FL)        // 21152 floats = 84608 B (2 blocks/SM)

typedef unsigned long long ull;

// Pairwise barrier between kh-partner warps (w and w^4): ids 1..4, 64 threads.
#define PAIRBAR(bid) asm volatile("bar.sync %0, 64;" :: "r"(bid) : "memory")

// Repacked stage-1 weights: g_wzr[k*Hk + j] = (wz, wr); float4 view gives
// (wz_j0, wr_j0, wz_j1, wr_j1) for a j-pair in one LDG.128.
__device__ __align__(16) float2 g_wzr[Hk * Hk];
// Row permutation: rows sorted by length DESCENDING (deterministic rank sort).
__device__ int g_perm[Bk];

__device__ __forceinline__ void fma2(ull& d, ull a, ull b) {
    asm("fma.rn.f32x2 %0, %1, %2, %0;" : "+l"(d) : "l"(a), "l"(b));
}
__device__ __forceinline__ void add2(ull& d, ull a) {
    asm("add.rn.f32x2 %0, %0, %1;" : "+l"(d) : "l"(a));
}
__device__ __forceinline__ ull pack2(float lo, float hi) {
    ull r; asm("mov.b64 %0, {%1, %2};" : "=l"(r) : "f"(lo), "f"(hi)); return r;
}
__device__ __forceinline__ float2 unpack2(ull p) {
    float2 f; asm("mov.b64 {%0, %1}, %2;" : "=f"(f.x), "=f"(f.y) : "l"(p)); return f;
}
__device__ __forceinline__ float sigmoidf_fast(float x) {
    return 1.0f / (1.0f + __expf(-x));
}
__device__ __forceinline__ float2 lds2v(uint32_t a) {
    float2 f;
    asm volatile("ld.shared.v2.f32 {%0,%1},[%2];" : "=f"(f.x), "=f"(f.y) : "r"(a));
    return f;
}
__device__ __forceinline__ void fma8s(float acc[8], float4 a0, float4 a1, float wv) {
    acc[0] = fmaf(a0.x, wv, acc[0]); acc[1] = fmaf(a0.y, wv, acc[1]);
    acc[2] = fmaf(a0.z, wv, acc[2]); acc[3] = fmaf(a0.w, wv, acc[3]);
    acc[4] = fmaf(a1.x, wv, acc[4]); acc[5] = fmaf(a1.y, wv, acc[5]);
    acc[6] = fmaf(a1.z, wv, acc[6]); acc[7] = fmaf(a1.w, wv, acc[7]);
}

__global__ void repack_kernel(const float* __restrict__ Wz,
                              const float* __restrict__ Wr) {
    int idx = blockIdx.x * blockDim.x + threadIdx.x;
    int k = idx >> 8, j = idx & (Hk - 1);
    g_wzr[idx] = make_float2(Wz[(NVk + k) * Hk + j], Wr[(NVk + k) * Hk + j]);
}

// Deterministic rank sort (descending by length, ties by index), PARALLEL:
// 16 blocks x 128 threads; each block caches all lengths in smem, each
// thread ranks one row. O(B) work per thread, spread over 16 SMs.
__global__ void rank_kernel(const int* __restrict__ lengths) {
    __shared__ int lens[Bk];
    for (int i = threadIdx.x; i < Bk; i += blockDim.x) lens[i] = lengths[i];
    __syncthreads();
    int i = blockIdx.x * blockDim.x + threadIdx.x;   // row to rank
    int li = lens[i];
    int rank = 0;
#pragma unroll 8
    for (int j = 0; j < Bk; j++) {
        int lj = lens[j];
        rank += (lj > li) || (lj == li && j < i);
    }
    g_perm[rank] = i;
}

// 256 blocks x 256 threads, 2 co-resident blocks/SM. Block b owns rows
// perm[8b..8b+8] (length-sorted, descending => LPT scheduling). Runs only
// tmax = max(len in group) GRU steps, then zero-fills the padded tail.
// Thread (jp, kh): columns j0=2jp, j1=j0+1; accumulates 8 rows over k-half
// [kh*128, +128); finalizes rows rfin = kh*4..+4 after pairwise exchange.
__global__ __launch_bounds__(256, 2)
void gru_decoder_kernel(
    const float* __restrict__ x_seq,
    const float* __restrict__ hidden,
    const float* __restrict__ tree,
    const float* __restrict__ graph,
    const int*   __restrict__ lengths,
    const float* __restrict__ Wcs, const float* __restrict__ bcs,
    const float* __restrict__ Wz,  const float* __restrict__ bz,
    const float* __restrict__ Wr,  const float* __restrict__ br,
    const float* __restrict__ Wh,  const float* __restrict__ bh,
    float* __restrict__ out)
{
    extern __shared__ __align__(16) float smf[];
    float* hsb  = smf;                       // hs[k*HSTR + r]
    float* rhb  = smf + RH_OFF;              // rh[k*HSTR + r]
    ull*   pexu = (ull*)(smf + PEX_OFF);     // exchange buffer
    float* cvb  = smf + PEX_OFF;             // prologue overlay (3072 floats)
    float* xw   = smf + XW_OFF;              // x-weights+bias [g][v(6)][j]
    float* latsm= smf + LAT_OFF;             // latents [r][j]
    float* xall = smf + XALL_OFF;            // x preload [(t*5+v)*8 + r]

    __shared__ int rowsm[Rk];                // permuted absolute row ids
    __shared__ int slensm[Rk];

    const int tid  = threadIdx.x;
    const int jp   = tid & 127;
    const int kh   = tid >> 7;
    const int j0   = jp << 1;
    const int rfin = kh << 2;
    const int rexp = (1 - kh) << 2;
    const int ep   = (1 - kh) << 1;
    const int op   = kh << 1;
    const int k0   = kh << 7;
    const int pbid = 1 + ((tid >> 5) & 3);

    float* out_newh = out;
    float* out_all  = out + Bk * Hk;
    float* out_seg  = out + Bk * Hk + Bk * Tk * OW;

    // ---- group rows via permutation ----
    if (tid < Rk) {
        int row = g_perm[blockIdx.x * Rk + tid];
        rowsm[tid]  = row;
        slensm[tid] = lengths[row];
    }
    __syncthreads();

    int rowr[4], slenr[4];
#pragma unroll
    for (int i = 0; i < 4; i++) {
        rowr[i]  = rowsm[rfin + i];
        slenr[i] = slensm[rfin + i];
    }
    int tmax = slensm[0];
#pragma unroll
    for (int r = 1; r < Rk; r++) tmax = max(tmax, slensm[r]);

    // ---- one-time loads ----
    for (int idx = tid; idx < XW_FL; idx += 256) {
        int g = idx / (6 * Hk);
        int vj = idx - g * 6 * Hk;
        int v = vj >> 8, j = vj & 255;
        const float* W = (g == 0) ? Wz : ((g == 1) ? Wr : Wh);
        const float* bb = (g == 0) ? bz : ((g == 1) ? br : bh);
        xw[idx] = (v < NVk) ? W[v * Hk + j] : bb[j];
    }
    for (int idx = tid; idx < Rk * Tk * NVk; idx += 256) {
        int r  = idx / (Tk * NVk);
        int tv = idx - r * (Tk * NVk);
        xall[tv * Rk + r] = x_seq[rowsm[r] * (Tk * NVk) + tv];
    }
    for (int idx = tid; idx < LAT_FL; idx += 256) {
        int r = idx >> 8, j = idx & 255;
        latsm[idx] = (j < Lk) ? tree[rowsm[r] * Lk + j]
                              : graph[rowsm[r] * Lk + (j - Lk)];
    }
    for (int idx = tid; idx < Rk * (Hk + Lk); idx += 256) {
        int r = idx / (Hk + Lk);
        int k = idx - r * (Hk + Lk);
        cvb[k * Rk + r] = (k < Hk) ? hidden[rowsm[r] * Hk + k]
                                   : graph[rowsm[r] * Lk + (k - Hk)];
    }
    __syncthreads();

    // h0 = relu(cv @ Wcs + bcs): thread covers column jc = tid, 8 rows
    {
        const int jc = tid;
        float acc[8];
        const float b0 = bcs[jc];
#pragma unroll
        for (int r = 0; r < 8; r++) acc[r] = b0;
        const float* pcs = Wcs + jc;
#pragma unroll 4
        for (int k = 0; k < Hk + Lk; k++) {
            float wv  = pcs[k * Hk];
            float4 a0 = *(const float4*)&cvb[k * Rk];
            float4 a1 = *(const float4*)&cvb[k * Rk + 4];
            fma8s(acc, a0, a1, wv);
        }
#pragma unroll
        for (int r = 0; r < 8; r++) hsb[jc * HSTR + r] = fmaxf(acc[r], 0.0f);
    }

    float segj0[4], segj1[4];
#pragma unroll
    for (int i = 0; i < 4; i++) { segj0[i] = -1e30f; segj1[i] = -1e30f; }

    const uint32_t smem_u32 = (uint32_t)__cvta_generic_to_shared(smf);
    const uint32_t xbase    = smem_u32 + (uint32_t)(XW_OFF + j0) * 4u;

    ull* pe = pexu + jp * ESTR + (1 - kh) * 8;
    const ull* po = pexu + jp * ESTR + kh * 8;

    const float4* pwbase  = reinterpret_cast<const float4*>(g_wzr) + (k0 << 7) + jp;
    const float2* pwhbase = reinterpret_cast<const float2*>(Wh + NVk * Hk) + (k0 << 7) + jp;

    float4 wp = pwbase[0];   // prefetch stage1 weights for t=0

    for (int t = 0; t < tmax; t++) {
        __syncthreads();   // prev-step hsb writes complete; pex reusable

        const float* xp = xall + t * (NVk * Rk) + rexp;

        // ---- stage 1: z & r partials (2 j x 8 rows over own k-half) ----
        ull az0[4], az1[4], ar0[4], ar1[4];
        {
            float2 bz2 = lds2v(xbase + 5u * 1024u);
            float2 br2 = lds2v(xbase + 6144u + 5u * 1024u);
            float vz0[4], vz1[4], vr0[4], vr1[4];
#pragma unroll
            for (int i = 0; i < 4; i++) {
                vz0[i] = bz2.x; vz1[i] = bz2.y; vr0[i] = br2.x; vr1[i] = br2.y;
            }
#pragma unroll
            for (int v = 0; v < NVk; v++) {
                float2 wz = lds2v(xbase + (unsigned)v * 1024u);
                float2 wr = lds2v(xbase + 6144u + (unsigned)v * 1024u);
#pragma unroll
                for (int i = 0; i < 4; i++) {
                    float xv = xp[v * Rk + i];
                    vz0[i] = fmaf(xv, wz.x, vz0[i]); vz1[i] = fmaf(xv, wz.y, vz1[i]);
                    vr0[i] = fmaf(xv, wr.x, vr0[i]); vr1[i] = fmaf(xv, wr.y, vr1[i]);
                }
            }
            az0[ep] = pack2(vz0[0], vz0[1]); az0[ep + 1] = pack2(vz0[2], vz0[3]);
            az1[ep] = pack2(vz1[0], vz1[1]); az1[ep + 1] = pack2(vz1[2], vz1[3]);
            ar0[ep] = pack2(vr0[0], vr0[1]); ar0[ep + 1] = pack2(vr0[2], vr0[3]);
            ar1[ep] = pack2(vr1[0], vr1[1]); ar1[ep + 1] = pack2(vr1[2], vr1[3]);
            az0[op] = 0; az0[op + 1] = 0; az1[op] = 0; az1[op + 1] = 0;
            ar0[op] = 0; ar0[op + 1] = 0; ar1[op] = 0; ar1[op + 1] = 0;
        }
        {
            const char* hp = (const char*)(hsb + k0 * HSTR);
            {   // peeled kk=0 with prefetched weights
                ulonglong2 hA = *(const ulonglong2*)hp;
                ulonglong2 hB = *(const ulonglong2*)(hp + 16);
                hp += HSTR * 4;
                ull wzz0 = pack2(wp.x, wp.x), wrr0 = pack2(wp.y, wp.y);
                ull wzz1 = pack2(wp.z, wp.z), wrr1 = pack2(wp.w, wp.w);
                fma2(az0[0], hA.x, wzz0); fma2(az0[1], hA.y, wzz0);
                fma2(az0[2], hB.x, wzz0); fma2(az0[3], hB.y, wzz0);
                fma2(az1[0], hA.x, wzz1); fma2(az1[1], hA.y, wzz1);
                fma2(az1[2], hB.x, wzz1); fma2(az1[3], hB.y, wzz1);
                fma2(ar0[0], hA.x, wrr0); fma2(ar0[1], hA.y, wrr0);
                fma2(ar0[2], hB.x, wrr0); fma2(ar0[3], hB.y, wrr0);
                fma2(ar1[0], hA.x, wrr1); fma2(ar1[1], hA.y, wrr1);
                fma2(ar1[2], hB.x, wrr1); fma2(ar1[3], hB.y, wrr1);
            }
            const float4* pw = pwbase + 128;
#pragma unroll 8
            for (int kk = 1; kk < 128; kk++) {
                float4 w = *pw; pw += 128;
                ulonglong2 hA = *(const ulonglong2*)hp;
                ulonglong2 hB = *(const ulonglong2*)(hp + 16);
                hp += HSTR * 4;
                ull wzz0 = pack2(w.x, w.x), wrr0 = pack2(w.y, w.y);
                ull wzz1 = pack2(w.z, w.z), wrr1 = pack2(w.w, w.w);
                fma2(az0[0], hA.x, wzz0); fma2(az0[1], hA.y, wzz0);
                fma2(az0[2], hB.x, wzz0); fma2(az0[3], hB.y, wzz0);
                fma2(az1[0], hA.x, wzz1); fma2(az1[1], hA.y, wzz1);
                fma2(az1[2], hB.x, wzz1); fma2(az1[3], hB.y, wzz1);
                fma2(ar0[0], hA.x, wrr0); fma2(ar0[1], hA.y, wrr0);
                fma2(ar0[2], hB.x, wrr0); fma2(ar0[3], hB.y, wrr0);
                fma2(ar1[0], hA.x, wrr1); fma2(ar1[1], hA.y, wrr1);
                fma2(ar1[2], hB.x, wrr1); fma2(ar1[3], hB.y, wrr1);
            }
        }
        pe[0] = az0[ep]; pe[1] = az0[ep + 1]; pe[2] = az1[ep]; pe[3] = az1[ep + 1];
        pe[4] = ar0[ep]; pe[5] = ar0[ep + 1]; pe[6] = ar1[ep]; pe[7] = ar1[ep + 1];
        PAIRBAR(pbid);

        float zv0[4], zv1[4];
        {
            add2(az0[op], po[0]); add2(az0[op + 1], po[1]);
            add2(az1[op], po[2]); add2(az1[op + 1], po[3]);
            add2(ar0[op], po[4]); add2(ar0[op + 1], po[5]);
            add2(ar1[op], po[6]); add2(ar1[op + 1], po[7]);
            float2 z0a = unpack2(az0[op]), z0b = unpack2(az0[op + 1]);
            float2 z1a = unpack2(az1[op]), z1b = unpack2(az1[op + 1]);
            zv0[0] = sigmoidf_fast(z0a.x); zv0[1] = sigmoidf_fast(z0a.y);
            zv0[2] = sigmoidf_fast(z0b.x); zv0[3] = sigmoidf_fast(z0b.y);
            zv1[0] = sigmoidf_fast(z1a.x); zv1[1] = sigmoidf_fast(z1a.y);
            zv1[2] = sigmoidf_fast(z1b.x); zv1[3] = sigmoidf_fast(z1b.y);
            float2 r0a = unpack2(ar0[op]), r0b = unpack2(ar0[op + 1]);
            float2 r1a = unpack2(ar1[op]), r1b = unpack2(ar1[op + 1]);
            float2 h0a = *(const float2*)&hsb[j0 * HSTR + rfin];
            float2 h0b = *(const float2*)&hsb[j0 * HSTR + rfin + 2];
            float2 h1a = *(const float2*)&hsb[(j0 + 1) * HSTR + rfin];
            float2 h1b = *(const float2*)&hsb[(j0 + 1) * HSTR + rfin + 2];
            *(ull*)&rhb[j0 * HSTR + rfin] =
                pack2(sigmoidf_fast(r0a.x) * h0a.x, sigmoidf_fast(r0a.y) * h0a.y);
            *(ull*)&rhb[j0 * HSTR + rfin + 2] =
                pack2(sigmoidf_fast(r0b.x) * h0b.x, sigmoidf_fast(r0b.y) * h0b.y);
            *(ull*)&rhb[(j0 + 1) * HSTR + rfin] =
                pack2(sigmoidf_fast(r1a.x) * h1a.x, sigmoidf_fast(r1a.y) * h1a.y);
            *(ull*)&rhb[(j0 + 1) * HSTR + rfin + 2] =
                pack2(sigmoidf_fast(r1b.x) * h1b.x, sigmoidf_fast(r1b.y) * h1b.y);
        }

        // ---- stage 2 x-part init (rhb-independent; before full sync) ----
        ull ah0[4], ah1[4];
        {
            float2 bh2 = lds2v(xbase + 12288u + 5u * 1024u);
            float vh0[4], vh1[4];
#pragma unroll
            for (int i = 0; i < 4; i++) { vh0[i] = bh2.x; vh1[i] = bh2.y; }
#pragma unroll
            for (int v = 0; v < NVk; v++) {
                float2 wh = lds2v(xbase + 12288u + (unsigned)v * 1024u);
#pragma unroll
                for (int i = 0; i < 4; i++) {
                    float xv = xp[v * Rk + i];
                    vh0[i] = fmaf(xv, wh.x, vh0[i]); vh1[i] = fmaf(xv, wh.y, vh1[i]);
                }
            }
            ah0[ep] = pack2(vh0[0], vh0[1]); ah0[ep + 1] = pack2(vh0[2], vh0[3]);
            ah1[ep] = pack2(vh1[0], vh1[1]); ah1[ep + 1] = pack2(vh1[2], vh1[3]);
            ah0[op] = 0; ah0[op + 1] = 0; ah1[op] = 0; ah1[op + 1] = 0;
        }
        float2 whp = pwhbase[0];   // prefetch stage2 weights behind barrier
        __syncthreads();           // rhb writes complete

        {
            const char* rp = (const char*)(rhb + k0 * HSTR);
            {   // peeled kk=0
                ulonglong2 rA = *(const ulonglong2*)rp;
                ulonglong2 rB = *(const ulonglong2*)(rp + 16);
                rp += HSTR * 4;
                ull whh0 = pack2(whp.x, whp.x), whh1 = pack2(whp.y, whp.y);
                fma2(ah0[0], rA.x, whh0); fma2(ah0[1], rA.y, whh0);
                fma2(ah0[2], rB.x, whh0); fma2(ah0[3], rB.y, whh0);
                fma2(ah1[0], rA.x, whh1); fma2(ah1[1], rA.y, whh1);
                fma2(ah1[2], rB.x, whh1); fma2(ah1[3], rB.y, whh1);
            }
            const float2* pwh = pwhbase + 128;
#pragma unroll 8
            for (int kk = 1; kk < 128; kk++) {
                float2 wh = *pwh; pwh += 128;
                ulonglong2 rA = *(const ulonglong2*)rp;
                ulonglong2 rB = *(const ulonglong2*)(rp + 16);
                rp += HSTR * 4;
                ull whh0 = pack2(wh.x, wh.x), whh1 = pack2(wh.y, wh.y);
                fma2(ah0[0], rA.x, whh0); fma2(ah0[1], rA.y, whh0);
                fma2(ah0[2], rB.x, whh0); fma2(ah0[3], rB.y, whh0);
                fma2(ah1[0], rA.x, whh1); fma2(ah1[1], rA.y, whh1);
                fma2(ah1[2], rB.x, whh1); fma2(ah1[3], rB.y, whh1);
            }
        }
        pe[0] = ah0[ep]; pe[1] = ah0[ep + 1]; pe[2] = ah1[ep]; pe[3] = ah1[ep + 1];
        PAIRBAR(pbid);

        // ---- combine + epilogue for own 2j x 4 rows ----
        {
            add2(ah0[op], po[0]); add2(ah0[op + 1], po[1]);
            add2(ah1[op], po[2]); add2(ah1[op + 1], po[3]);
            float2 p0a = unpack2(ah0[op]), p0b = unpack2(ah0[op + 1]);
            float2 p1a = unpack2(ah1[op]), p1b = unpack2(ah1[op + 1]);
            float pre0[4] = {tanhf(p0a.x), tanhf(p0a.y), tanhf(p0b.x), tanhf(p0b.y)};
            float pre1[4] = {tanhf(p1a.x), tanhf(p1a.y), tanhf(p1b.x), tanhf(p1b.y)};
            float2 h0a = *(const float2*)&hsb[j0 * HSTR + rfin];
            float2 h0b = *(const float2*)&hsb[j0 * HSTR + rfin + 2];
            float2 h1a = *(const float2*)&hsb[(j0 + 1) * HSTR + rfin];
            float2 h1b = *(const float2*)&hsb[(j0 + 1) * HSTR + rfin + 2];
            float hold0[4] = {h0a.x, h0a.y, h0b.x, h0b.y};
            float hold1[4] = {h1a.x, h1a.y, h1b.x, h1b.y};
            float hn0[4], hn1[4];
#pragma unroll
            for (int i = 0; i < 4; i++) {
                hn0[i] = (1.0f - zv0[i]) * hold0[i] + zv0[i] * pre0[i];
                hn1[i] = (1.0f - zv1[i]) * hold1[i] + zv1[i] * pre1[i];
            }
            *(ull*)&hsb[j0 * HSTR + rfin]           = pack2(hn0[0], hn0[1]);
            *(ull*)&hsb[j0 * HSTR + rfin + 2]       = pack2(hn0[2], hn0[3]);
            *(ull*)&hsb[(j0 + 1) * HSTR + rfin]     = pack2(hn1[0], hn1[1]);
            *(ull*)&hsb[(j0 + 1) * HSTR + rfin + 2] = pack2(hn1[2], hn1[3]);
#pragma unroll
            for (int i = 0; i < 4; i++) {
                int  row   = rowr[i];
                bool valid = (t < slenr[i]);
                int  base  = row * (Tk * OW) + t * OW;
                float2 latv = *(const float2*)&latsm[(rfin + i) * Hk + j0];
                *(float2*)&out_all[base + j0] =
                    valid ? make_float2(hn0[i], hn1[i]) : make_float2(0.f, 0.f);
                *(float2*)&out_all[base + Hk + j0] =
                    valid ? latv : make_float2(0.f, 0.f);
                if (valid) {
                    segj0[i] = fmaxf(segj0[i], hn0[i]);
                    segj1[i] = fmaxf(segj1[i], hn1[i]);
                }
                if (t == slenr[i] - 1)
                    *(float2*)&out_newh[row * Hk + j0] = make_float2(hn0[i], hn1[i]);
            }
        }
        wp = pwbase[0];   // prefetch next-t stage1 weights behind barrier
    }

    // ---- zero-fill padded tail t in [tmax, Tk) (pure stores) ----
    const float2 z2 = make_float2(0.f, 0.f);
    for (int t = tmax; t < Tk; t++) {
#pragma unroll
        for (int i = 0; i < 4; i++) {
            int base = rowr[i] * (Tk * OW) + t * OW;
            *(float2*)&out_all[base + j0]      = z2;
            *(float2*)&out_all[base + Hk + j0] = z2;
        }
    }

#pragma unroll
    for (int i = 0; i < 4; i++)
        *(float2*)&out_seg[rowr[i] * Hk + j0] = make_float2(segj0[i], segj1[i]);
}

extern "C" void kernel_launch(void* const* d_in, const int* in_sizes, int n_in,
                              void* d_out, int out_size) {
    const float* x_seq   = (const float*)d_in[0];
    const float* hidden  = (const float*)d_in[1];
    const float* tree    = (const float*)d_in[2];
    const float* graph   = (const float*)d_in[3];
    const int*   lengths = (const int*)  d_in[4];
    const float* Wcs = (const float*)d_in[5];
    const float* bcs = (const float*)d_in[6];
    const float* Wz  = (const float*)d_in[7];
    const float* bz  = (const float*)d_in[8];
    const float* Wr  = (const float*)d_in[9];
    const float* br  = (const float*)d_in[10];
    const float* Wh  = (const float*)d_in[11];
    const float* bh  = (const float*)d_in[12];
    float* out = (float*)d_out;

    cudaFuncSetAttribute(gru_decoder_kernel,
                         cudaFuncAttributeMaxDynamicSharedMemorySize,
                         SMEM_F * (int)sizeof(float));
    rank_kernel<<<Bk / 128, 128>>>(lengths);
    repack_kernel<<<Hk * Hk / 256, 256>>>(Wz, Wr);
    gru_decoder_kernel<<<Bk / Rk, 256, SMEM_F * sizeof(float)>>>(
        x_seq, hidden, tree, graph, lengths,
        Wcs, bcs, Wz, bz, Wr, br, Wh, bh, out);
}

// round 17
// speedup vs baseline: 2.4981x; 1.0337x over previous
#include <cuda_runtime.h>
#include <cstdint>

#define Bk 2048
#define Tk 100
#define Hk 256
#define Lk 128
#define NVk 5
#define Rk 8        // batch rows per block
#define OW 512
#define HSTR 12     // hs/rh k-row stride in floats (48B)
#define ESTR 17     // pex entry stride in ull

#define RH_OFF   (Hk * HSTR)                 // 3072 floats
#define PEX_OFF  (2 * Hk * HSTR)             // 6144 floats
#define PEX_FL   (128 * ESTR * 2)            // 4352 floats (2176 ull)
#define XW_OFF   (PEX_OFF + PEX_FL)          // 10496
#define XW_FL    (3 * 6 * Hk)                // 4608
#define LAT_OFF  (XW_OFF + XW_FL)            // 15104
#define LAT_FL   (Rk * Hk)                   // 2048
#define XALL_OFF (LAT_OFF + LAT_FL)          // 17152
#define XALL_FL  (Tk * NVk * Rk)             // 4000
#define SMEM_F   (XALL_OFF + XALL_FL)        // 21152 floats = 84608 B (2 blocks/SM)

typedef unsigned long long ull;

// Pairwise barrier between kh-partner warps (w and w^4): ids 1..4, 64 threads.
#define PAIRBAR(bid) asm volatile("bar.sync %0, 64;" :: "r"(bid) : "memory")

// Repacked stage-1 weights: g_wzr[k*Hk + j] = (wz, wr); float4 view gives
// (wz_j0, wr_j0, wz_j1, wr_j1) for a j-pair in one LDG.128.
__device__ __align__(16) float2 g_wzr[Hk * Hk];
// Row permutation: rows sorted by length DESCENDING (deterministic rank sort).
__device__ int g_perm[Bk];

__device__ __forceinline__ void fma2(ull& d, ull a, ull b) {
    asm("fma.rn.f32x2 %0, %1, %2, %0;" : "+l"(d) : "l"(a), "l"(b));
}
__device__ __forceinline__ void add2(ull& d, ull a) {
    asm("add.rn.f32x2 %0, %0, %1;" : "+l"(d) : "l"(a));
}
__device__ __forceinline__ ull pack2(float lo, float hi) {
    ull r; asm("mov.b64 %0, {%1, %2};" : "=l"(r) : "f"(lo), "f"(hi)); return r;
}
__device__ __forceinline__ float2 unpack2(ull p) {
    float2 f; asm("mov.b64 {%0, %1}, %2;" : "=f"(f.x), "=f"(f.y) : "l"(p)); return f;
}
__device__ __forceinline__ float sigmoidf_fast(float x) {
    return 1.0f / (1.0f + __expf(-x));
}
__device__ __forceinline__ float2 lds2v(uint32_t a) {
    float2 f;
    asm volatile("ld.shared.v2.f32 {%0,%1},[%2];" : "=f"(f.x), "=f"(f.y) : "r"(a));
    return f;
}
__device__ __forceinline__ void fma8s(float acc[8], float4 a0, float4 a1, float wv) {
    acc[0] = fmaf(a0.x, wv, acc[0]); acc[1] = fmaf(a0.y, wv, acc[1]);
    acc[2] = fmaf(a0.z, wv, acc[2]); acc[3] = fmaf(a0.w, wv, acc[3]);
    acc[4] = fmaf(a1.x, wv, acc[4]); acc[5] = fmaf(a1.y, wv, acc[5]);
    acc[6] = fmaf(a1.z, wv, acc[6]); acc[7] = fmaf(a1.w, wv, acc[7]);
}

__global__ void repack_kernel(const float* __restrict__ Wz,
                              const float* __restrict__ Wr) {
    int idx = blockIdx.x * blockDim.x + threadIdx.x;
    int k = idx >> 8, j = idx & (Hk - 1);
    g_wzr[idx] = make_float2(Wz[(NVk + k) * Hk + j], Wr[(NVk + k) * Hk + j]);
}

// Deterministic rank sort (descending by length, ties by index), parallel.
__global__ void rank_kernel(const int* __restrict__ lengths) {
    __shared__ int lens[Bk];
    for (int i = threadIdx.x; i < Bk; i += blockDim.x) lens[i] = lengths[i];
    __syncthreads();
    int i = blockIdx.x * blockDim.x + threadIdx.x;   // row to rank
    int li = lens[i];
    int rank = 0;
#pragma unroll 8
    for (int j = 0; j < Bk; j++) {
        int lj = lens[j];
        rank += (lj > li) || (lj == li && j < i);
    }
    g_perm[rank] = i;
}

// Block b -> length-sorted group g, balancing per-SM load. Classic placement
// puts blocks b and b+148 on the same SM; blocks 108..147 are solo.
//   solo blocks (108..147)  -> groups 0..39   (longest; solo runs faster)
//   paired: block b (<108)  -> group 40+b, partner b+148 -> group 255-b
//   => per-SM pair load ~constant (~85 steps) instead of 142-0.78s.
__device__ __forceinline__ int group_of_block(int b) {
    if (b >= 108 && b < 148) return b - 108;
    return (b < 108) ? (40 + b) : (403 - b);
}

// 256 blocks x 256 threads, 2 co-resident blocks/SM. Block processes rows
// perm[8g..8g+8]; runs only tmax = max(len in group) GRU steps, then
// zero-fills the padded tail. Thread (jp, kh): columns j0=2jp, j1=j0+1;
// accumulates 8 rows over k-half [kh*128, +128); finalizes rows kh*4..+4.
__global__ __launch_bounds__(256, 2)
void gru_decoder_kernel(
    const float* __restrict__ x_seq,
    const float* __restrict__ hidden,
    const float* __restrict__ tree,
    const float* __restrict__ graph,
    const int*   __restrict__ lengths,
    const float* __restrict__ Wcs, const float* __restrict__ bcs,
    const float* __restrict__ Wz,  const float* __restrict__ bz,
    const float* __restrict__ Wr,  const float* __restrict__ br,
    const float* __restrict__ Wh,  const float* __restrict__ bh,
    float* __restrict__ out)
{
    extern __shared__ __align__(16) float smf[];
    float* hsb  = smf;                       // hs[k*HSTR + r]
    float* rhb  = smf + RH_OFF;              // rh[k*HSTR + r]
    ull*   pexu = (ull*)(smf + PEX_OFF);     // exchange buffer
    float* cvb  = smf + PEX_OFF;             // prologue overlay (3072 floats)
    float* xw   = smf + XW_OFF;              // x-weights+bias [g][v(6)][j]
    float* latsm= smf + LAT_OFF;             // latents [r][j]
    float* xall = smf + XALL_OFF;            // x preload [(t*5+v)*8 + r]

    __shared__ int rowsm[Rk];                // permuted absolute row ids
    __shared__ int slensm[Rk];

    const int tid  = threadIdx.x;
    const int jp   = tid & 127;
    const int kh   = tid >> 7;
    const int j0   = jp << 1;
    const int rfin = kh << 2;
    const int rexp = (1 - kh) << 2;
    const int ep   = (1 - kh) << 1;
    const int op   = kh << 1;
    const int k0   = kh << 7;
    const int pbid = 1 + ((tid >> 5) & 3);

    float* out_newh = out;
    float* out_all  = out + Bk * Hk;
    float* out_seg  = out + Bk * Hk + Bk * Tk * OW;

    // ---- group rows via permutation + balanced block->group map ----
    const int grp = group_of_block(blockIdx.x);
    if (tid < Rk) {
        int row = g_perm[grp * Rk + tid];
        rowsm[tid]  = row;
        slensm[tid] = lengths[row];
    }
    __syncthreads();

    int rowr[4], slenr[4];
#pragma unroll
    for (int i = 0; i < 4; i++) {
        rowr[i]  = rowsm[rfin + i];
        slenr[i] = slensm[rfin + i];
    }
    int tmax = slensm[0];
#pragma unroll
    for (int r = 1; r < Rk; r++) tmax = max(tmax, slensm[r]);

    // ---- one-time loads ----
    for (int idx = tid; idx < XW_FL; idx += 256) {
        int g = idx / (6 * Hk);
        int vj = idx - g * 6 * Hk;
        int v = vj >> 8, j = vj & 255;
        const float* W = (g == 0) ? Wz : ((g == 1) ? Wr : Wh);
        const float* bb = (g == 0) ? bz : ((g == 1) ? br : bh);
        xw[idx] = (v < NVk) ? W[v * Hk + j] : bb[j];
    }
    for (int idx = tid; idx < Rk * Tk * NVk; idx += 256) {
        int r  = idx / (Tk * NVk);
        int tv = idx - r * (Tk * NVk);
        xall[tv * Rk + r] = x_seq[rowsm[r] * (Tk * NVk) + tv];
    }
    for (int idx = tid; idx < LAT_FL; idx += 256) {
        int r = idx >> 8, j = idx & 255;
        latsm[idx] = (j < Lk) ? tree[rowsm[r] * Lk + j]
                              : graph[rowsm[r] * Lk + (j - Lk)];
    }
    for (int idx = tid; idx < Rk * (Hk + Lk); idx += 256) {
        int r = idx / (Hk + Lk);
        int k = idx - r * (Hk + Lk);
        cvb[k * Rk + r] = (k < Hk) ? hidden[rowsm[r] * Hk + k]
                                   : graph[rowsm[r] * Lk + (k - Hk)];
    }
    __syncthreads();

    // h0 = relu(cv @ Wcs + bcs): thread covers column jc = tid, 8 rows
    {
        const int jc = tid;
        float acc[8];
        const float b0 = bcs[jc];
#pragma unroll
        for (int r = 0; r < 8; r++) acc[r] = b0;
        const float* pcs = Wcs + jc;
#pragma unroll 4
        for (int k = 0; k < Hk + Lk; k++) {
            float wv  = pcs[k * Hk];
            float4 a0 = *(const float4*)&cvb[k * Rk];
            float4 a1 = *(const float4*)&cvb[k * Rk + 4];
            fma8s(acc, a0, a1, wv);
        }
#pragma unroll
        for (int r = 0; r < 8; r++) hsb[jc * HSTR + r] = fmaxf(acc[r], 0.0f);
    }

    float segj0[4], segj1[4];
#pragma unroll
    for (int i = 0; i < 4; i++) { segj0[i] = -1e30f; segj1[i] = -1e30f; }

    const uint32_t smem_u32 = (uint32_t)__cvta_generic_to_shared(smf);
    const uint32_t xbase    = smem_u32 + (uint32_t)(XW_OFF + j0) * 4u;

    ull* pe = pexu + jp * ESTR + (1 - kh) * 8;
    const ull* po = pexu + jp * ESTR + kh * 8;

    const float4* pwbase  = reinterpret_cast<const float4*>(g_wzr) + (k0 << 7) + jp;
    const float2* pwhbase = reinterpret_cast<const float2*>(Wh + NVk * Hk) + (k0 << 7) + jp;

    float4 wp = pwbase[0];   // prefetch stage1 weights for t=0

    for (int t = 0; t < tmax; t++) {
        __syncthreads();   // prev-step hsb writes complete; pex reusable

        const float* xp = xall + t * (NVk * Rk) + rexp;

        // ---- stage 1: z & r partials (2 j x 8 rows over own k-half) ----
        ull az0[4], az1[4], ar0[4], ar1[4];
        {
            float2 bz2 = lds2v(xbase + 5u * 1024u);
            float2 br2 = lds2v(xbase + 6144u + 5u * 1024u);
            float vz0[4], vz1[4], vr0[4], vr1[4];
#pragma unroll
            for (int i = 0; i < 4; i++) {
                vz0[i] = bz2.x; vz1[i] = bz2.y; vr0[i] = br2.x; vr1[i] = br2.y;
            }
#pragma unroll
            for (int v = 0; v < NVk; v++) {
                float2 wz = lds2v(xbase + (unsigned)v * 1024u);
                float2 wr = lds2v(xbase + 6144u + (unsigned)v * 1024u);
#pragma unroll
                for (int i = 0; i < 4; i++) {
                    float xv = xp[v * Rk + i];
                    vz0[i] = fmaf(xv, wz.x, vz0[i]); vz1[i] = fmaf(xv, wz.y, vz1[i]);
                    vr0[i] = fmaf(xv, wr.x, vr0[i]); vr1[i] = fmaf(xv, wr.y, vr1[i]);
                }
            }
            az0[ep] = pack2(vz0[0], vz0[1]); az0[ep + 1] = pack2(vz0[2], vz0[3]);
            az1[ep] = pack2(vz1[0], vz1[1]); az1[ep + 1] = pack2(vz1[2], vz1[3]);
            ar0[ep] = pack2(vr0[0], vr0[1]); ar0[ep + 1] = pack2(vr0[2], vr0[3]);
            ar1[ep] = pack2(vr1[0], vr1[1]); ar1[ep + 1] = pack2(vr1[2], vr1[3]);
            az0[op] = 0; az0[op + 1] = 0; az1[op] = 0; az1[op + 1] = 0;
            ar0[op] = 0; ar0[op + 1] = 0; ar1[op] = 0; ar1[op + 1] = 0;
        }
        {
            const char* hp = (const char*)(hsb + k0 * HSTR);
            {   // peeled kk=0 with prefetched weights
                ulonglong2 hA = *(const ulonglong2*)hp;
                ulonglong2 hB = *(const ulonglong2*)(hp + 16);
                hp += HSTR * 4;
                ull wzz0 = pack2(wp.x, wp.x), wrr0 = pack2(wp.y, wp.y);
                ull wzz1 = pack2(wp.z, wp.z), wrr1 = pack2(wp.w, wp.w);
                fma2(az0[0], hA.x, wzz0); fma2(az0[1], hA.y, wzz0);
                fma2(az0[2], hB.x, wzz0); fma2(az0[3], hB.y, wzz0);
                fma2(az1[0], hA.x, wzz1); fma2(az1[1], hA.y, wzz1);
                fma2(az1[2], hB.x, wzz1); fma2(az1[3], hB.y, wzz1);
                fma2(ar0[0], hA.x, wrr0); fma2(ar0[1], hA.y, wrr0);
                fma2(ar0[2], hB.x, wrr0); fma2(ar0[3], hB.y, wrr0);
                fma2(ar1[0], hA.x, wrr1); fma2(ar1[1], hA.y, wrr1);
                fma2(ar1[2], hB.x, wrr1); fma2(ar1[3], hB.y, wrr1);
            }
            const float4* pw = pwbase + 128;
#pragma unroll 8
            for (int kk = 1; kk < 128; kk++) {
                float4 w = *pw; pw += 128;
                ulonglong2 hA = *(const ulonglong2*)hp;
                ulonglong2 hB = *(const ulonglong2*)(hp + 16);
                hp += HSTR * 4;
                ull wzz0 = pack2(w.x, w.x), wrr0 = pack2(w.y, w.y);
                ull wzz1 = pack2(w.z, w.z), wrr1 = pack2(w.w, w.w);
                fma2(az0[0], hA.x, wzz0); fma2(az0[1], hA.y, wzz0);
                fma2(az0[2], hB.x, wzz0); fma2(az0[3], hB.y, wzz0);
                fma2(az1[0], hA.x, wzz1); fma2(az1[1], hA.y, wzz1);
                fma2(az1[2], hB.x, wzz1); fma2(az1[3], hB.y, wzz1);
                fma2(ar0[0], hA.x, wrr0); fma2(ar0[1], hA.y, wrr0);
                fma2(ar0[2], hB.x, wrr0); fma2(ar0[3], hB.y, wrr0);
                fma2(ar1[0], hA.x, wrr1); fma2(ar1[1], hA.y, wrr1);
                fma2(ar1[2], hB.x, wrr1); fma2(ar1[3], hB.y, wrr1);
            }
        }
        pe[0] = az0[ep]; pe[1] = az0[ep + 1]; pe[2] = az1[ep]; pe[3] = az1[ep + 1];
        pe[4] = ar0[ep]; pe[5] = ar0[ep + 1]; pe[6] = ar1[ep]; pe[7] = ar1[ep + 1];
        PAIRBAR(pbid);

        float zv0[4], zv1[4];
        {
            add2(az0[op], po[0]); add2(az0[op + 1], po[1]);
            add2(az1[op], po[2]); add2(az1[op + 1], po[3]);
            add2(ar0[op], po[4]); add2(ar0[op + 1], po[5]);
            add2(ar1[op], po[6]); add2(ar1[op + 1], po[7]);
            float2 z0a = unpack2(az0[op]), z0b = unpack2(az0[op + 1]);
            float2 z1a = unpack2(az1[op]), z1b = unpack2(az1[op + 1]);
            zv0[0] = sigmoidf_fast(z0a.x); zv0[1] = sigmoidf_fast(z0a.y);
            zv0[2] = sigmoidf_fast(z0b.x); zv0[3] = sigmoidf_fast(z0b.y);
            zv1[0] = sigmoidf_fast(z1a.x); zv1[1] = sigmoidf_fast(z1a.y);
            zv1[2] = sigmoidf_fast(z1b.x); zv1[3] = sigmoidf_fast(z1b.y);
            float2 r0a = unpack2(ar0[op]), r0b = unpack2(ar0[op + 1]);
            float2 r1a = unpack2(ar1[op]), r1b = unpack2(ar1[op + 1]);
            float2 h0a = *(const float2*)&hsb[j0 * HSTR + rfin];
            float2 h0b = *(const float2*)&hsb[j0 * HSTR + rfin + 2];
            float2 h1a = *(const float2*)&hsb[(j0 + 1) * HSTR + rfin];
            float2 h1b = *(const float2*)&hsb[(j0 + 1) * HSTR + rfin + 2];
            *(ull*)&rhb[j0 * HSTR + rfin] =
                pack2(sigmoidf_fast(r0a.x) * h0a.x, sigmoidf_fast(r0a.y) * h0a.y);
            *(ull*)&rhb[j0 * HSTR + rfin + 2] =
                pack2(sigmoidf_fast(r0b.x) * h0b.x, sigmoidf_fast(r0b.y) * h0b.y);
            *(ull*)&rhb[(j0 + 1) * HSTR + rfin] =
                pack2(sigmoidf_fast(r1a.x) * h1a.x, sigmoidf_fast(r1a.y) * h1a.y);
            *(ull*)&rhb[(j0 + 1) * HSTR + rfin + 2] =
                pack2(sigmoidf_fast(r1b.x) * h1b.x, sigmoidf_fast(r1b.y) * h1b.y);
        }

        // ---- stage 2 x-part init (rhb-independent; before full sync) ----
        ull ah0[4], ah1[4];
        {
            float2 bh2 = lds2v(xbase + 12288u + 5u * 1024u);
            float vh0[4], vh1[4];
#pragma unroll
            for (int i = 0; i < 4; i++) { vh0[i] = bh2.x; vh1[i] = bh2.y; }
#pragma unroll
            for (int v = 0; v < NVk; v++) {
                float2 wh = lds2v(xbase + 12288u + (unsigned)v * 1024u);
#pragma unroll
                for (int i = 0; i < 4; i++) {
                    float xv = xp[v * Rk + i];
                    vh0[i] = fmaf(xv, wh.x, vh0[i]); vh1[i] = fmaf(xv, wh.y, vh1[i]);
                }
            }
            ah0[ep] = pack2(vh0[0], vh0[1]); ah0[ep + 1] = pack2(vh0[2], vh0[3]);
            ah1[ep] = pack2(vh1[0], vh1[1]); ah1[ep + 1] = pack2(vh1[2], vh1[3]);
            ah0[op] = 0; ah0[op + 1] = 0; ah1[op] = 0; ah1[op + 1] = 0;
        }
        float2 whp = pwhbase[0];   // prefetch stage2 weights behind barrier
        __syncthreads();           // rhb writes complete

        {
            const char* rp = (const char*)(rhb + k0 * HSTR);
            {   // peeled kk=0
                ulonglong2 rA = *(const ulonglong2*)rp;
                ulonglong2 rB = *(const ulonglong2*)(rp + 16);
                rp += HSTR * 4;
                ull whh0 = pack2(whp.x, whp.x), whh1 = pack2(whp.y, whp.y);
                fma2(ah0[0], rA.x, whh0); fma2(ah0[1], rA.y, whh0);
                fma2(ah0[2], rB.x, whh0); fma2(ah0[3], rB.y, whh0);
                fma2(ah1[0], rA.x, whh1); fma2(ah1[1], rA.y, whh1);
                fma2(ah1[2], rB.x, whh1); fma2(ah1[3], rB.y, whh1);
            }
            const float2* pwh = pwhbase + 128;
#pragma unroll 8
            for (int kk = 1; kk < 128; kk++) {
                float2 wh = *pwh; pwh += 128;
                ulonglong2 rA = *(const ulonglong2*)rp;
                ulonglong2 rB = *(const ulonglong2*)(rp + 16);
                rp += HSTR * 4;
                ull whh0 = pack2(wh.x, wh.x), whh1 = pack2(wh.y, wh.y);
                fma2(ah0[0], rA.x, whh0); fma2(ah0[1], rA.y, whh0);
                fma2(ah0[2], rB.x, whh0); fma2(ah0[3], rB.y, whh0);
                fma2(ah1[0], rA.x, whh1); fma2(ah1[1], rA.y, whh1);
                fma2(ah1[2], rB.x, whh1); fma2(ah1[3], rB.y, whh1);
            }
        }
        pe[0] = ah0[ep]; pe[1] = ah0[ep + 1]; pe[2] = ah1[ep]; pe[3] = ah1[ep + 1];
        PAIRBAR(pbid);

        // ---- combine + epilogue for own 2j x 4 rows ----
        {
            add2(ah0[op], po[0]); add2(ah0[op + 1], po[1]);
            add2(ah1[op], po[2]); add2(ah1[op + 1], po[3]);
            float2 p0a = unpack2(ah0[op]), p0b = unpack2(ah0[op + 1]);
            float2 p1a = unpack2(ah1[op]), p1b = unpack2(ah1[op + 1]);
            float pre0[4] = {tanhf(p0a.x), tanhf(p0a.y), tanhf(p0b.x), tanhf(p0b.y)};
            float pre1[4] = {tanhf(p1a.x), tanhf(p1a.y), tanhf(p1b.x), tanhf(p1b.y)};
            float2 h0a = *(const float2*)&hsb[j0 * HSTR + rfin];
            float2 h0b = *(const float2*)&hsb[j0 * HSTR + rfin + 2];
            float2 h1a = *(const float2*)&hsb[(j0 + 1) * HSTR + rfin];
            float2 h1b = *(const float2*)&hsb[(j0 + 1) * HSTR + rfin + 2];
            float hold0[4] = {h0a.x, h0a.y, h0b.x, h0b.y};
            float hold1[4] = {h1a.x, h1a.y, h1b.x, h1b.y};
            float hn0[4], hn1[4];
#pragma unroll
            for (int i = 0; i < 4; i++) {
                hn0[i] = (1.0f - zv0[i]) * hold0[i] + zv0[i] * pre0[i];
                hn1[i] = (1.0f - zv1[i]) * hold1[i] + zv1[i] * pre1[i];
            }
            *(ull*)&hsb[j0 * HSTR + rfin]           = pack2(hn0[0], hn0[1]);
            *(ull*)&hsb[j0 * HSTR + rfin + 2]       = pack2(hn0[2], hn0[3]);
            *(ull*)&hsb[(j0 + 1) * HSTR + rfin]     = pack2(hn1[0], hn1[1]);
            *(ull*)&hsb[(j0 + 1) * HSTR + rfin + 2] = pack2(hn1[2], hn1[3]);
#pragma unroll
            for (int i = 0; i < 4; i++) {
                int  row   = rowr[i];
                bool valid = (t < slenr[i]);
                int  base  = row * (Tk * OW) + t * OW;
                float2 latv = *(const float2*)&latsm[(rfin + i) * Hk + j0];
                *(float2*)&out_all[base + j0] =
                    valid ? make_float2(hn0[i], hn1[i]) : make_float2(0.f, 0.f);
                *(float2*)&out_all[base + Hk + j0] =
                    valid ? latv : make_float2(0.f, 0.f);
                if (valid) {
                    segj0[i] = fmaxf(segj0[i], hn0[i]);
                    segj1[i] = fmaxf(segj1[i], hn1[i]);
                }
                if (t == slenr[i] - 1)
                    *(float2*)&out_newh[row * Hk + j0] = make_float2(hn0[i], hn1[i]);
            }
        }
        wp = pwbase[0];   // prefetch next-t stage1 weights behind barrier
    }

    // ---- zero-fill padded tail t in [tmax, Tk) (pure stores) ----
    const float2 z2 = make_float2(0.f, 0.f);
    for (int t = tmax; t < Tk; t++) {
#pragma unroll
        for (int i = 0; i < 4; i++) {
            int base = rowr[i] * (Tk * OW) + t * OW;
            *(float2*)&out_all[base + j0]      = z2;
            *(float2*)&out_all[base + Hk + j0] = z2;
        }
    }

#pragma unroll
    for (int i = 0; i < 4; i++)
        *(float2*)&out_seg[rowr[i] * Hk + j0] = make_float2(segj0[i], segj1[i]);
}

extern "C" void kernel_launch(void* const* d_in, const int* in_sizes, int n_in,
                              void* d_out, int out_size) {
    const float* x_seq   = (const float*)d_in[0];
    const float* hidden  = (const float*)d_in[1];
    const float* tree    = (const float*)d_in[2];
    const float* graph   = (const float*)d_in[3];
    const int*   lengths = (const int*)  d_in[4];
    const float* Wcs = (const float*)d_in[5];
    const float* bcs = (const float*)d_in[6];
    const float* Wz  = (const float*)d_in[7];
    const float* bz  = (const float*)d_in[8];
    const float* Wr  = (const float*)d_in[9];
    const float* br  = (const float*)d_in[10];
    const float* Wh  = (const float*)d_in[11];
    const float* bh  = (const float*)d_in[12];
    float* out = (float*)d_out;

    cudaFuncSetAttribute(gru_decoder_kernel,
                         cudaFuncAttributeMaxDynamicSharedMemorySize,
                         SMEM_F * (int)sizeof(float));
    rank_kernel<<<Bk / 128, 128>>>(lengths);
    repack_kernel<<<Hk * Hk / 256, 256>>>(Wz, Wr);
    gru_decoder_kernel<<<Bk / Rk, 256, SMEM_F * sizeof(float)>>>(
        x_seq, hidden, tree, graph, lengths,
        Wcs, bcs, Wz, bz, Wr, br, Wh, bh, out);
}